// round 13
// baseline (speedup 1.0000x reference)
#include <cuda_runtime.h>
#include <cuda_bf16.h>
#include <mma.h>
#include <math.h>
#include <stdint.h>

using namespace nvcuda;

// Problem constants
#define NB     4
#define TSEQ   2048
#define DMODEL 1024
#define DFF    4096
#define NTOK   (NB * TSEQ)   // 8192

typedef __nv_bfloat16 bf16;

// ---------------------------------------------------------------------------
// Scratch (device globals — no allocations allowed)
// ---------------------------------------------------------------------------
__device__ bf16  g_Xb  [NTOK * DMODEL];
__device__ bf16  g_WQt [DMODEL * DMODEL];            // [N,K] bf16
__device__ bf16  g_WKt [DMODEL * DMODEL];
__device__ bf16  g_WVt [DMODEL * DMODEL];
__device__ bf16  g_WOt [DMODEL * DMODEL];
__device__ bf16  g_W1t [DFF * DMODEL];               // [4096,1024]
__device__ bf16  g_W2t [DMODEL * DFF];               // [1024,4096]
__device__ bf16  g_Qb  [NTOK * DMODEL];
__device__ bf16  g_Kb  [NTOK * DMODEL];
__device__ bf16  g_Vb  [NTOK * DMODEL];
__device__ bf16  g_VTb [(size_t)NB * DMODEL * TSEQ]; // V^T per batch [D,T]
__device__ bf16  g_Pb  [(size_t)NB * TSEQ * TSEQ];   // probs bf16
__device__ bf16  g_AOb [NTOK * DMODEL];
__device__ bf16  g_H1b [NTOK * DMODEL];
__device__ bf16  g_FFb [(size_t)NTOK * DFF];
__device__ float g_S   [(size_t)NB * TSEQ * TSEQ];   // fp32 logits
__device__ float g_O   [NTOK * DMODEL];
__device__ float g_H1  [NTOK * DMODEL];
__device__ float g_H2  [NTOK * DMODEL];

// ---------------------------------------------------------------------------
// PTX helpers
// ---------------------------------------------------------------------------
__device__ __forceinline__ uint32_t smem_u32(const void* p) {
    return (uint32_t)__cvta_generic_to_shared(p);
}
__device__ __forceinline__ void mbar_init(uint32_t addr, uint32_t count) {
    asm volatile("mbarrier.init.shared.b64 [%0], %1;" :: "r"(addr), "r"(count) : "memory");
}
// arrive + add expected-tx; issued PER THREAD right before that thread's copy,
// so every complete_tx is preceded (program order) by a matching expect_tx.
__device__ __forceinline__ void mbar_arrive_expect(uint32_t addr, uint32_t bytes) {
    asm volatile("mbarrier.arrive.expect_tx.shared.b64 _, [%0], %1;"
                 :: "r"(addr), "r"(bytes) : "memory");
}
__device__ __forceinline__ void mbar_wait(uint32_t addr, uint32_t parity) {
    asm volatile(
        "{\n\t.reg .pred P;\n"
        "WAIT_%=:\n\t"
        "mbarrier.try_wait.parity.acquire.cta.shared::cta.b64 P, [%0], %1;\n\t"
        "@!P bra WAIT_%=;\n\t}"
        :: "r"(addr), "r"(parity) : "memory");
}
__device__ __forceinline__ void bulk_g2s(uint32_t dst, const void* src,
                                         uint32_t bytes, uint32_t mbar) {
    asm volatile(
        "cp.async.bulk.shared::cluster.global.mbarrier::complete_tx::bytes [%0], [%1], %2, [%3];"
        :: "r"(dst), "l"(src), "r"(bytes), "r"(mbar) : "memory");
}

// ---------------------------------------------------------------------------
// bf16 tensor-core GEMM: C = alpha * A @ B^T [+bias][gelu]
// Block tile 256x128, BK=64, 3-stage cp.async.bulk + mbarrier pipeline.
// 256 threads, 8 warps as 4(M) x 2(N); warp tile 64x64 (4x4 m16n16k16 frags)
// -> 16 MMAs per 8 fragment loads (2x the ILP of the 64x32 config).
// Per stage: 384 bulk row copies (A:256, B:128); threads 0-127 own an A-row
// AND a B-row (2 arrivals each), threads 128-255 own an A-row (1 arrival).
// mbarrier arrive count = 384 = 128*2 + 128*1; every copy's complete_tx is
// preceded in program order by that thread's own arrive.expect_tx(128).
// (R11 bug: an extra plain arrive made 512 arrivals vs count 384 -> fault.)
//   EPI: 0=none, 1=+bias, 2=+bias+GELU ; OUTB: bf16 out (else fp32)
//   CSKIP: skip tiles fully above diagonal ; CK: clamp K to (by+1)*256
// ---------------------------------------------------------------------------
template <int EPI, bool OUTB, bool CSKIP, bool CK>
__global__ __launch_bounds__(256, 1)
void bfgemm_kernel(const bf16* __restrict__ A, const bf16* __restrict__ B,
                   const float* __restrict__ bias, void* __restrict__ Cv,
                   int M, int N, int K, float alpha,
                   long long sA, long long sB, long long sC)
{
    constexpr int BM = 256, BN = 128, BK = 64;
    constexpr int ASTB = 144;                     // smem row stride, bytes
    constexpr int AST  = 72;                      // bf16 elems (mult of 8)
    constexpr int A_B  = BM * ASTB;               // 36864 B
    constexpr int B_B  = BN * ASTB;               // 18432 B
    constexpr int STAGE_B = A_B + B_B;            // 55296 B per stage

    const int bx = blockIdx.x, by = blockIdx.y, bz = blockIdx.z;
    if (CSKIP && bx >= (by + 1) * 2) return;      // tile fully above diagonal

    A += (long long)bz * sA;
    B += (long long)bz * sB;

    const int m0 = by * BM, n0 = bx * BN;
    const int kEnd = CK ? min(K, (by + 1) * BM) : K;
    const int nIter = kEnd / BK;

    extern __shared__ __align__(16) char smem_raw[];
    const uint32_t smemBase = smem_u32(smem_raw);
    const uint32_t tile0 = (smemBase + 1023) & ~1023u;

    __shared__ __align__(8) uint64_t s_mbar[3];
    const int tid = threadIdx.x;
    const int wid = tid >> 5;
    const int wy = wid >> 1;                      // 0..3 -> M (64 rows each)
    const int wx = wid & 1;                       // 0..1 -> N (64 cols each)

    if (tid == 0) {
        mbar_init(smem_u32(&s_mbar[0]), 384);
        mbar_init(smem_u32(&s_mbar[1]), 384);
        mbar_init(smem_u32(&s_mbar[2]), 384);
    }
    __syncthreads();
    const uint32_t mb0 = smem_u32(&s_mbar[0]);

    // copy ownership: every thread owns A row tid; threads <128 also own B row tid
    const bf16* aRow = A + (long long)(m0 + tid) * K;
    const uint32_t aOff = (uint32_t)tid * ASTB;
    const bool hasB = tid < BN;
    const bf16* bRow = hasB ? (B + (long long)(n0 + tid) * K) : nullptr;
    const uint32_t bOff = (uint32_t)A_B + (uint32_t)tid * ASTB;

    auto load_stage = [&](int it, int s) {
        const uint32_t mb = mb0 + s * 8;
        const uint32_t base = tile0 + (uint32_t)s * STAGE_B;
        const long long k = (long long)it * BK;
        mbar_arrive_expect(mb, 128);
        bulk_g2s(base + aOff, aRow + k, 128, mb);
        if (hasB) {
            mbar_arrive_expect(mb, 128);
            bulk_g2s(base + bOff, bRow + k, 128, mb);
        }
    };

    wmma::fragment<wmma::accumulator, 16, 16, 16, float> c_frag[4][4];
    #pragma unroll
    for (int i = 0; i < 4; i++)
        #pragma unroll
        for (int j = 0; j < 4; j++)
            wmma::fill_fragment(c_frag[i][j], 0.0f);

    // ---- prologue: 2 stages in flight ----
    load_stage(0, 0);
    if (nIter > 1) load_stage(1, 1);

    uint32_t ph[3] = {0, 0, 0};

    for (int it = 0; it < nIter; it++) {
        const int s = it % 3;
        mbar_wait(mb0 + s * 8, ph[s]);
        ph[s] ^= 1;

        // refill chunk it+2 into stage (it+2)%3 == (it-1)%3 — safe: the
        // loop-end __syncthreads of iteration it-1 ordered all reads of it.
        if (it + 2 < nIter) load_stage(it + 2, (it + 2) % 3);

        const bf16* As = (const bf16*)(smem_raw + (tile0 - smemBase) + s * STAGE_B);
        const bf16* Bs = (const bf16*)((const char*)As + A_B);

        #pragma unroll
        for (int kk = 0; kk < BK; kk += 16) {
            wmma::fragment<wmma::matrix_a, 16, 16, 16, bf16, wmma::row_major> a_frag[4];
            wmma::fragment<wmma::matrix_b, 16, 16, 16, bf16, wmma::col_major> b_frag[4];
            #pragma unroll
            for (int i = 0; i < 4; i++)
                wmma::load_matrix_sync(a_frag[i], &As[(wy * 64 + i * 16) * AST + kk], AST);
            #pragma unroll
            for (int j = 0; j < 4; j++)
                wmma::load_matrix_sync(b_frag[j], &Bs[(wx * 64 + j * 16) * AST + kk], AST);
            #pragma unroll
            for (int i = 0; i < 4; i++)
                #pragma unroll
                for (int j = 0; j < 4; j++)
                    wmma::mma_sync(c_frag[i][j], a_frag[i], b_frag[j], c_frag[i][j]);
        }
        __syncthreads();
    }

    // ---- epilogue: 2 phases of 128 rows through fp32 smem staging ----
    constexpr int STG = 136;
    float* Stage = (float*)smem_raw;
    #pragma unroll
    for (int p = 0; p < 2; p++) {
        if ((wy >> 1) == p) {
            #pragma unroll
            for (int i = 0; i < 4; i++)
                #pragma unroll
                for (int j = 0; j < 4; j++)
                    wmma::store_matrix_sync(&Stage[((wy & 1) * 64 + i * 16) * STG + wx * 64 + j * 16],
                                            c_frag[i][j], STG, wmma::mem_row_major);
        }
        __syncthreads();
        #pragma unroll
        for (int i = 0; i < 16; i++) {
            int f = tid + i * 256;                // 4096 float4 over 128x128
            int r = f >> 5, c4 = f & 31;
            float4 v = *(const float4*)&Stage[r * STG + c4 * 4];
            float o[4] = {v.x, v.y, v.z, v.w};
            #pragma unroll
            for (int e = 0; e < 4; e++) {
                float x = o[e] * alpha;
                if (EPI >= 1) x += bias[n0 + c4 * 4 + e];
                if (EPI == 2) x = 0.5f * x * (1.0f + erff(x * 0.70710678118654752f));
                o[e] = x;
            }
            const long long off = (long long)bz * sC + (long long)(m0 + p * 128 + r) * N + n0 + c4 * 4;
            if (OUTB) {
                ushort4 u;
                u.x = __bfloat16_as_ushort(__float2bfloat16_rn(o[0]));
                u.y = __bfloat16_as_ushort(__float2bfloat16_rn(o[1]));
                u.z = __bfloat16_as_ushort(__float2bfloat16_rn(o[2]));
                u.w = __bfloat16_as_ushort(__float2bfloat16_rn(o[3]));
                *(ushort4*)((bf16*)Cv + off) = u;
            } else {
                *(float4*)((float*)Cv + off) = *(const float4*)o;
            }
        }
        __syncthreads();
    }
}

static const int GEMM_SMEM = 1024 + 3 * 55296;    // 166912 B (epilogue needs 69632)

// ---------------------------------------------------------------------------
// fp32 -> bf16
// ---------------------------------------------------------------------------
__global__ __launch_bounds__(256)
void f2bf_kernel(const float* __restrict__ in, bf16* __restrict__ out, int n)
{
    int i = (blockIdx.x * 256 + threadIdx.x) * 4;
    if (i >= n) return;
    float4 v = *(const float4*)(in + i);
    ushort4 o;
    o.x = __bfloat16_as_ushort(__float2bfloat16_rn(v.x));
    o.y = __bfloat16_as_ushort(__float2bfloat16_rn(v.y));
    o.z = __bfloat16_as_ushort(__float2bfloat16_rn(v.z));
    o.w = __bfloat16_as_ushort(__float2bfloat16_rn(v.w));
    *(ushort4*)(out + i) = o;
}

// ---------------------------------------------------------------------------
// fp32 [R,C] -> bf16 [C,R]  (32x32 tiles)
// ---------------------------------------------------------------------------
__global__ __launch_bounds__(256)
void trans_f2bf_kernel(const float* __restrict__ in, bf16* __restrict__ out, int R, int C)
{
    __shared__ float t[32][33];
    const int bx = blockIdx.x, by = blockIdx.y;
    const int x = threadIdx.x & 31, y = threadIdx.x >> 5;
    #pragma unroll
    for (int i = 0; i < 4; i++) {
        int r = by * 32 + y + i * 8;
        t[y + i * 8][x] = in[(long long)r * C + bx * 32 + x];
    }
    __syncthreads();
    #pragma unroll
    for (int i = 0; i < 4; i++) {
        int cc = bx * 32 + y + i * 8;
        int rr = by * 32 + x;
        out[(long long)cc * R + rr] = __float2bfloat16_rn(t[x][y + i * 8]);
    }
}

// ---------------------------------------------------------------------------
// bf16 batched transpose: [B][T][D] -> [B][D][T]
// ---------------------------------------------------------------------------
__global__ __launch_bounds__(256)
void transb_kernel(const bf16* __restrict__ in, bf16* __restrict__ out)
{
    __shared__ bf16 t[32][33];
    const int bx = blockIdx.x, by = blockIdx.y, bz = blockIdx.z;
    const bf16* pi = in + (long long)bz * TSEQ * DMODEL;
    bf16* po = out + (long long)bz * DMODEL * TSEQ;
    const int x = threadIdx.x & 31, y = threadIdx.x >> 5;
    #pragma unroll
    for (int i = 0; i < 4; i++)
        t[y + i * 8][x] = pi[(long long)(by * 32 + y + i * 8) * DMODEL + bx * 32 + x];
    __syncthreads();
    #pragma unroll
    for (int i = 0; i < 4; i++)
        po[(long long)(bx * 32 + y + i * 8) * TSEQ + by * 32 + x] = t[x][y + i * 8];
}

// ---------------------------------------------------------------------------
// Causal softmax (row staged in smem): fp32 logits -> bf16 probs, zero tail
// ---------------------------------------------------------------------------
__global__ __launch_bounds__(256)
void softmax_causal_kernel(const float* __restrict__ S, bf16* __restrict__ P)
{
    __shared__ float buf[TSEQ];
    __shared__ float red[256];
    const int t = blockIdx.x, b = blockIdx.y;
    const float* row = S + ((long long)b * TSEQ + t) * TSEQ;
    bf16* prow = P + ((long long)b * TSEQ + t) * TSEQ;
    const int len = t + 1;
    const int tid = threadIdx.x;

    float m = -1e30f;
    for (int s = tid; s < len; s += 256) { float v = row[s]; buf[s] = v; m = fmaxf(m, v); }
    red[tid] = m; __syncthreads();
    for (int o = 128; o > 0; o >>= 1) {
        if (tid < o) red[tid] = fmaxf(red[tid], red[tid + o]);
        __syncthreads();
    }
    m = red[0];
    __syncthreads();

    float sum = 0.0f;
    for (int s = tid; s < len; s += 256) { float e = expf(buf[s] - m); buf[s] = e; sum += e; }
    red[tid] = sum; __syncthreads();
    for (int o = 128; o > 0; o >>= 1) {
        if (tid < o) red[tid] += red[tid + o];
        __syncthreads();
    }
    const float inv = 1.0f / red[0];

    for (int s = tid; s < len; s += 256)        prow[s] = __float2bfloat16_rn(buf[s] * inv);
    for (int s = len + tid; s < TSEQ; s += 256) prow[s] = __float2bfloat16_rn(0.0f);
}

// ---------------------------------------------------------------------------
// out = LayerNorm(Xa + Xb) * g + be ; optional bf16 copy
// ---------------------------------------------------------------------------
__global__ __launch_bounds__(256)
void add_ln_kernel(const float* __restrict__ Xa, const float* __restrict__ Xb,
                   const float* __restrict__ g,  const float* __restrict__ be,
                   float* __restrict__ out, bf16* __restrict__ out_bf)
{
    const int row = blockIdx.x;
    const int tid = threadIdx.x;
    const float* pa = Xa + (long long)row * DMODEL;
    const float* pb = Xb + (long long)row * DMODEL;

    float x[4];
    float s1 = 0.0f, s2 = 0.0f;
    #pragma unroll
    for (int i = 0; i < 4; i++) {
        int c = tid + i * 256;
        x[i] = pa[c] + pb[c];
        s1 += x[i];
        s2 += x[i] * x[i];
    }
    __shared__ float r1[256], r2[256];
    r1[tid] = s1; r2[tid] = s2; __syncthreads();
    for (int o = 128; o > 0; o >>= 1) {
        if (tid < o) { r1[tid] += r1[tid + o]; r2[tid] += r2[tid + o]; }
        __syncthreads();
    }
    const float mu  = r1[0] * (1.0f / DMODEL);
    const float var = r2[0] * (1.0f / DMODEL) - mu * mu;
    const float inv = rsqrtf(var + 1e-5f);

    float* po = out + (long long)row * DMODEL;
    #pragma unroll
    for (int i = 0; i < 4; i++) {
        int c = tid + i * 256;
        float v = (x[i] - mu) * inv * g[c] + be[c];
        po[c] = v;
        if (out_bf) out_bf[(long long)row * DMODEL + c] = __float2bfloat16_rn(v);
    }
}

// ---------------------------------------------------------------------------
// Host launch
// ---------------------------------------------------------------------------
extern "C" void kernel_launch(void* const* d_in, const int* in_sizes, int n_in,
                              void* d_out, int out_size)
{
    (void)in_sizes; (void)n_in; (void)out_size;
    const float* X   = (const float*)d_in[0];
    const float* WQ  = (const float*)d_in[1];
    const float* bQ  = (const float*)d_in[2];
    const float* WK  = (const float*)d_in[3];
    const float* bK  = (const float*)d_in[4];
    const float* WV  = (const float*)d_in[5];
    const float* bV  = (const float*)d_in[6];
    const float* WO  = (const float*)d_in[7];
    const float* bO  = (const float*)d_in[8];
    const float* W1  = (const float*)d_in[9];
    const float* b1  = (const float*)d_in[10];
    const float* W2  = (const float*)d_in[11];
    const float* b2  = (const float*)d_in[12];
    const float* g1  = (const float*)d_in[13];
    const float* be1 = (const float*)d_in[14];
    const float* g2  = (const float*)d_in[15];
    const float* be2 = (const float*)d_in[16];
    float* out = (float*)d_out;

    bf16 *Xb, *WQt, *WKt, *WVt, *WOt, *W1t, *W2t, *Qb, *Kb, *Vb, *VTb, *Pb, *AOb, *H1b, *FFb;
    float *S, *O, *H1, *H2;
    cudaGetSymbolAddress((void**)&Xb,  g_Xb);
    cudaGetSymbolAddress((void**)&WQt, g_WQt);
    cudaGetSymbolAddress((void**)&WKt, g_WKt);
    cudaGetSymbolAddress((void**)&WVt, g_WVt);
    cudaGetSymbolAddress((void**)&WOt, g_WOt);
    cudaGetSymbolAddress((void**)&W1t, g_W1t);
    cudaGetSymbolAddress((void**)&W2t, g_W2t);
    cudaGetSymbolAddress((void**)&Qb,  g_Qb);
    cudaGetSymbolAddress((void**)&Kb,  g_Kb);
    cudaGetSymbolAddress((void**)&Vb,  g_Vb);
    cudaGetSymbolAddress((void**)&VTb, g_VTb);
    cudaGetSymbolAddress((void**)&Pb,  g_Pb);
    cudaGetSymbolAddress((void**)&AOb, g_AOb);
    cudaGetSymbolAddress((void**)&H1b, g_H1b);
    cudaGetSymbolAddress((void**)&FFb, g_FFb);
    cudaGetSymbolAddress((void**)&S,   g_S);
    cudaGetSymbolAddress((void**)&O,   g_O);
    cudaGetSymbolAddress((void**)&H1,  g_H1);
    cudaGetSymbolAddress((void**)&H2,  g_H2);

    cudaFuncSetAttribute(bfgemm_kernel<1, true,  false, false>, cudaFuncAttributeMaxDynamicSharedMemorySize, GEMM_SMEM);
    cudaFuncSetAttribute(bfgemm_kernel<0, false, true,  false>, cudaFuncAttributeMaxDynamicSharedMemorySize, GEMM_SMEM);
    cudaFuncSetAttribute(bfgemm_kernel<0, true,  false, true >, cudaFuncAttributeMaxDynamicSharedMemorySize, GEMM_SMEM);
    cudaFuncSetAttribute(bfgemm_kernel<1, false, false, false>, cudaFuncAttributeMaxDynamicSharedMemorySize, GEMM_SMEM);
    cudaFuncSetAttribute(bfgemm_kernel<2, true,  false, false>, cudaFuncAttributeMaxDynamicSharedMemorySize, GEMM_SMEM);

    const dim3 blk256(256);

    // ---- convert / transpose inputs ----
    f2bf_kernel<<<NTOK * DMODEL / 1024, blk256>>>(X, Xb, NTOK * DMODEL);
    trans_f2bf_kernel<<<dim3(32, 32),  blk256>>>(WQ, WQt, DMODEL, DMODEL);
    trans_f2bf_kernel<<<dim3(32, 32),  blk256>>>(WK, WKt, DMODEL, DMODEL);
    trans_f2bf_kernel<<<dim3(32, 32),  blk256>>>(WV, WVt, DMODEL, DMODEL);
    trans_f2bf_kernel<<<dim3(32, 32),  blk256>>>(WO, WOt, DMODEL, DMODEL);
    trans_f2bf_kernel<<<dim3(128, 32), blk256>>>(W1, W1t, DMODEL, DFF);   // -> [4096,1024]
    trans_f2bf_kernel<<<dim3(32, 128), blk256>>>(W2, W2t, DFF, DMODEL);   // -> [1024,4096]

    const dim3 gProj(DMODEL / 128, NTOK / 256);            // 8 x 32
    const dim3 gS(TSEQ / 128, TSEQ / 256, NB);             // 16 x 8 x 4
    const dim3 gAV(DMODEL / 128, TSEQ / 256, NB);          // 8 x 8 x 4
    const dim3 gFF1(DFF / 128, NTOK / 256);                // 32 x 32
    const dim3 gFF2(DMODEL / 128, NTOK / 256);             // 8 x 32

    const long long sQK = (long long)TSEQ * DMODEL;
    const long long sSS = (long long)TSEQ * TSEQ;

    // QKV projections -> bf16
    bfgemm_kernel<1, true, false, false><<<gProj, blk256, GEMM_SMEM>>>(Xb, WQt, bQ, Qb, NTOK, DMODEL, DMODEL, 1.0f, 0, 0, 0);
    bfgemm_kernel<1, true, false, false><<<gProj, blk256, GEMM_SMEM>>>(Xb, WKt, bK, Kb, NTOK, DMODEL, DMODEL, 1.0f, 0, 0, 0);
    bfgemm_kernel<1, true, false, false><<<gProj, blk256, GEMM_SMEM>>>(Xb, WVt, bV, Vb, NTOK, DMODEL, DMODEL, 1.0f, 0, 0, 0);

    // V^T per batch for A@V
    transb_kernel<<<dim3(DMODEL / 32, TSEQ / 32, NB), blk256>>>(Vb, VTb);

    // scores = (Q @ K^T)/sqrt(D) -> fp32
    bfgemm_kernel<0, false, true, false><<<gS, blk256, GEMM_SMEM>>>(Qb, Kb, nullptr, S, TSEQ, TSEQ, DMODEL,
                                                                    0.03125f, sQK, sQK, sSS);

    // causal softmax -> bf16 probs
    softmax_causal_kernel<<<dim3(TSEQ, NB), blk256>>>(S, Pb);

    // attn = P @ V  (B = V^T [D,T]) -> bf16
    bfgemm_kernel<0, true, false, true><<<gAV, blk256, GEMM_SMEM>>>(Pb, VTb, nullptr, AOb, TSEQ, DMODEL, TSEQ,
                                                                    1.0f, sSS, (long long)DMODEL * TSEQ, sQK);

    // O projection -> fp32
    bfgemm_kernel<1, false, false, false><<<gProj, blk256, GEMM_SMEM>>>(AOb, WOt, bO, O, NTOK, DMODEL, DMODEL, 1.0f, 0, 0, 0);

    // H1 = LN(O + X)
    add_ln_kernel<<<NTOK, blk256>>>(O, X, g1, be1, H1, H1b);

    // FF = gelu(H1 @ W1 + b1) -> bf16
    bfgemm_kernel<2, true, false, false><<<gFF1, blk256, GEMM_SMEM>>>(H1b, W1t, b1, FFb, NTOK, DFF, DMODEL, 1.0f, 0, 0, 0);

    // H2 = FF @ W2 + b2 -> fp32
    bfgemm_kernel<1, false, false, false><<<gFF2, blk256, GEMM_SMEM>>>(FFb, W2t, b2, H2, NTOK, DMODEL, DFF, 1.0f, 0, 0, 0);

    // out = LN(H2 + H1)
    add_ln_kernel<<<NTOK, blk256>>>(H2, H1, g2, be2, out, nullptr);
}

// round 14
// speedup vs baseline: 1.2226x; 1.2226x over previous
#include <cuda_runtime.h>
#include <cuda_bf16.h>
#include <mma.h>
#include <math.h>
#include <stdint.h>

using namespace nvcuda;

// Problem constants
#define NB     4
#define TSEQ   2048
#define DMODEL 1024
#define DFF    4096
#define NTOK   (NB * TSEQ)   // 8192
#define DQKV   3072          // fused QKV width

typedef __nv_bfloat16 bf16;

// ---------------------------------------------------------------------------
// Scratch (device globals — no allocations allowed)
// ---------------------------------------------------------------------------
__device__ bf16  g_Xb  [NTOK * DMODEL];
__device__ bf16  g_Wqkv[DQKV * DMODEL];              // concat [3072,1024] [N,K]
__device__ float g_bqkv[DQKV];
__device__ bf16  g_WOt [DMODEL * DMODEL];
__device__ bf16  g_W1t [DFF * DMODEL];               // [4096,1024]
__device__ bf16  g_W2t [DMODEL * DFF];               // [1024,4096]
__device__ bf16  g_QKV [(size_t)NTOK * DQKV];        // fused Q|K|V rows
__device__ bf16  g_VTb [(size_t)NB * DMODEL * TSEQ]; // V^T per batch [D,T]
__device__ bf16  g_Pb  [(size_t)NB * TSEQ * TSEQ];   // probs bf16
__device__ bf16  g_AOb [NTOK * DMODEL];
__device__ bf16  g_H1b [NTOK * DMODEL];
__device__ bf16  g_FFb [(size_t)NTOK * DFF];
__device__ float g_S   [(size_t)NB * TSEQ * TSEQ];   // fp32 logits
__device__ float g_O   [NTOK * DMODEL];
__device__ float g_H1  [NTOK * DMODEL];
__device__ float g_H2  [NTOK * DMODEL];

// ---------------------------------------------------------------------------
// PTX helpers
// ---------------------------------------------------------------------------
__device__ __forceinline__ uint32_t smem_u32(const void* p) {
    return (uint32_t)__cvta_generic_to_shared(p);
}
__device__ __forceinline__ void mbar_init(uint32_t addr, uint32_t count) {
    asm volatile("mbarrier.init.shared.b64 [%0], %1;" :: "r"(addr), "r"(count) : "memory");
}
__device__ __forceinline__ void mbar_arrive_expect(uint32_t addr, uint32_t bytes) {
    asm volatile("mbarrier.arrive.expect_tx.shared.b64 _, [%0], %1;"
                 :: "r"(addr), "r"(bytes) : "memory");
}
__device__ __forceinline__ void mbar_wait(uint32_t addr, uint32_t parity) {
    asm volatile(
        "{\n\t.reg .pred P;\n"
        "WAIT_%=:\n\t"
        "mbarrier.try_wait.parity.acquire.cta.shared::cta.b64 P, [%0], %1;\n\t"
        "@!P bra WAIT_%=;\n\t}"
        :: "r"(addr), "r"(parity) : "memory");
}
__device__ __forceinline__ void bulk_g2s(uint32_t dst, const void* src,
                                         uint32_t bytes, uint32_t mbar) {
    asm volatile(
        "cp.async.bulk.shared::cluster.global.mbarrier::complete_tx::bytes [%0], [%1], %2, [%3];"
        :: "r"(dst), "l"(src), "r"(bytes), "r"(mbar) : "memory");
}

// ---------------------------------------------------------------------------
// bf16 tensor-core GEMM: C = alpha * A @ B^T [+bias][gelu]   (R10 core)
// Block tile 128x128, BK=64, 3-stage cp.async.bulk + mbarrier pipeline.
// 256 threads, 8 warps (2M x 4N, warp tile 64x32), 2 CTAs/SM.
// Generalized with lda/ldb so operands can be strided views (fused QKV).
//   EPI: 0=none, 1=+bias, 2=+bias+GELU ; OUTB: bf16 out (else fp32)
//   CSKIP: skip tiles above diagonal ; CK: clamp K to (by+1)*128
// ---------------------------------------------------------------------------
template <int EPI, bool OUTB, bool CSKIP, bool CK>
__global__ __launch_bounds__(256, 2)
void bfgemm_kernel(const bf16* __restrict__ A, int lda,
                   const bf16* __restrict__ B, int ldb,
                   const float* __restrict__ bias, void* __restrict__ Cv,
                   int M, int N, int K, float alpha,
                   long long sA, long long sB, long long sC)
{
    constexpr int BK = 64;
    constexpr int ASTB = 144;                     // smem row stride, bytes
    constexpr int AST  = 72;                      // bf16 elems (mult of 8)
    constexpr int OP_B = 128 * ASTB;              // 18432 B per operand
    constexpr int STAGE_B = 2 * OP_B;             // 36864 B per stage

    const int bx = blockIdx.x, by = blockIdx.y, bz = blockIdx.z;
    if (CSKIP && bx > by) return;

    A += (long long)bz * sA;
    B += (long long)bz * sB;

    const int m0 = by * 128, n0 = bx * 128;
    const int kEnd = CK ? min(K, (by + 1) * 128) : K;
    const int nIter = kEnd / BK;

    extern __shared__ __align__(16) char smem_raw[];
    const uint32_t smemBase = smem_u32(smem_raw);
    const uint32_t tile0 = (smemBase + 1023) & ~1023u;

    __shared__ __align__(8) uint64_t s_mbar[3];
    const int tid = threadIdx.x;
    const int wid = tid >> 5;
    const int wy = wid >> 2;                      // 0..1 -> M (64 rows)
    const int wx = wid & 3;                       // 0..3 -> N (32 cols)

    if (tid == 0) {
        mbar_init(smem_u32(&s_mbar[0]), 256);
        mbar_init(smem_u32(&s_mbar[1]), 256);
        mbar_init(smem_u32(&s_mbar[2]), 256);
    }
    __syncthreads();
    const uint32_t mb0 = smem_u32(&s_mbar[0]);

    // each thread owns one 128B row copy per stage
    const bool isA = tid < 128;
    const int rrow = isA ? tid : tid - 128;
    const bf16* gbase = isA ? (A + (long long)(m0 + rrow) * lda)
                            : (B + (long long)(n0 + rrow) * ldb);
    const uint32_t sOff = (isA ? 0u : (uint32_t)OP_B) + (uint32_t)rrow * ASTB;

    auto load_stage = [&](int it, int s) {
        const uint32_t mb = mb0 + s * 8;
        mbar_arrive_expect(mb, 128);              // own expect precedes own copy
        bulk_g2s(tile0 + (uint32_t)s * STAGE_B + sOff,
                 gbase + (long long)it * BK, 128, mb);
    };

    wmma::fragment<wmma::accumulator, 16, 16, 16, float> c_frag[4][2];
    #pragma unroll
    for (int i = 0; i < 4; i++)
        #pragma unroll
        for (int j = 0; j < 2; j++)
            wmma::fill_fragment(c_frag[i][j], 0.0f);

    // ---- prologue: 2 stages in flight ----
    load_stage(0, 0);
    if (nIter > 1) load_stage(1, 1);

    uint32_t ph[3] = {0, 0, 0};

    for (int it = 0; it < nIter; it++) {
        const int s = it % 3;
        mbar_wait(mb0 + s * 8, ph[s]);
        ph[s] ^= 1;

        // refill chunk it+2 into stage (it+2)%3 == (it-1)%3 — safe: the
        // loop-end __syncthreads of iteration it-1 ordered all reads of it.
        if (it + 2 < nIter) load_stage(it + 2, (it + 2) % 3);

        const bf16* As = (const bf16*)(smem_raw + (tile0 - smemBase) + s * STAGE_B);
        const bf16* Bs = (const bf16*)((const char*)As + OP_B);

        #pragma unroll
        for (int kk = 0; kk < BK; kk += 16) {
            wmma::fragment<wmma::matrix_a, 16, 16, 16, bf16, wmma::row_major> a_frag[4];
            wmma::fragment<wmma::matrix_b, 16, 16, 16, bf16, wmma::col_major> b_frag[2];
            #pragma unroll
            for (int i = 0; i < 4; i++)
                wmma::load_matrix_sync(a_frag[i], &As[(wy * 64 + i * 16) * AST + kk], AST);
            #pragma unroll
            for (int j = 0; j < 2; j++)
                wmma::load_matrix_sync(b_frag[j], &Bs[(wx * 32 + j * 16) * AST + kk], AST);
            #pragma unroll
            for (int i = 0; i < 4; i++)
                #pragma unroll
                for (int j = 0; j < 2; j++)
                    wmma::mma_sync(c_frag[i][j], a_frag[i], b_frag[j], c_frag[i][j]);
        }
        __syncthreads();
    }

    // ---- epilogue: two phases of 64 rows through fp32 smem staging ----
    constexpr int STG = 136;
    float* Stage = (float*)smem_raw;
    #pragma unroll
    for (int p = 0; p < 2; p++) {
        if (wy == p) {
            #pragma unroll
            for (int i = 0; i < 4; i++)
                #pragma unroll
                for (int j = 0; j < 2; j++)
                    wmma::store_matrix_sync(&Stage[(i * 16) * STG + wx * 32 + j * 16],
                                            c_frag[i][j], STG, wmma::mem_row_major);
        }
        __syncthreads();
        #pragma unroll
        for (int i = 0; i < 8; i++) {
            int f = tid + i * 256;                // 2048 float4 over 64x128
            int r = f >> 5, c4 = f & 31;
            float4 v = *(const float4*)&Stage[r * STG + c4 * 4];
            float o[4] = {v.x, v.y, v.z, v.w};
            #pragma unroll
            for (int e = 0; e < 4; e++) {
                float x = o[e] * alpha;
                if (EPI >= 1) x += bias[n0 + c4 * 4 + e];
                if (EPI == 2) x = 0.5f * x * (1.0f + erff(x * 0.70710678118654752f));
                o[e] = x;
            }
            const long long off = (long long)bz * sC + (long long)(m0 + p * 64 + r) * N + n0 + c4 * 4;
            if (OUTB) {
                ushort4 u;
                u.x = __bfloat16_as_ushort(__float2bfloat16_rn(o[0]));
                u.y = __bfloat16_as_ushort(__float2bfloat16_rn(o[1]));
                u.z = __bfloat16_as_ushort(__float2bfloat16_rn(o[2]));
                u.w = __bfloat16_as_ushort(__float2bfloat16_rn(o[3]));
                *(ushort4*)((bf16*)Cv + off) = u;
            } else {
                *(float4*)((float*)Cv + off) = *(const float4*)o;
            }
        }
        __syncthreads();
    }
}

static const int GEMM_SMEM = 1024 + 3 * 36864;    // 111616 B -> 2 CTAs/SM

// ---------------------------------------------------------------------------
// fp32 -> bf16
// ---------------------------------------------------------------------------
__global__ __launch_bounds__(256)
void f2bf_kernel(const float* __restrict__ in, bf16* __restrict__ out, int n)
{
    int i = (blockIdx.x * 256 + threadIdx.x) * 4;
    if (i >= n) return;
    float4 v = *(const float4*)(in + i);
    ushort4 o;
    o.x = __bfloat16_as_ushort(__float2bfloat16_rn(v.x));
    o.y = __bfloat16_as_ushort(__float2bfloat16_rn(v.y));
    o.z = __bfloat16_as_ushort(__float2bfloat16_rn(v.z));
    o.w = __bfloat16_as_ushort(__float2bfloat16_rn(v.w));
    *(ushort4*)(out + i) = o;
}

// ---------------------------------------------------------------------------
// fp32 [R,C] -> bf16 [C,R] written at out + colOffset rows (for QKV concat)
// ---------------------------------------------------------------------------
__global__ __launch_bounds__(256)
void trans_f2bf_kernel(const float* __restrict__ in, bf16* __restrict__ out, int R, int C)
{
    __shared__ float t[32][33];
    const int bx = blockIdx.x, by = blockIdx.y;
    const int x = threadIdx.x & 31, y = threadIdx.x >> 5;
    #pragma unroll
    for (int i = 0; i < 4; i++) {
        int r = by * 32 + y + i * 8;
        t[y + i * 8][x] = in[(long long)r * C + bx * 32 + x];
    }
    __syncthreads();
    #pragma unroll
    for (int i = 0; i < 4; i++) {
        int cc = bx * 32 + y + i * 8;
        int rr = by * 32 + x;
        out[(long long)cc * R + rr] = __float2bfloat16_rn(t[x][y + i * 8]);
    }
}

// ---------------------------------------------------------------------------
// concat 3 fp32 vectors of DMODEL into one [3072]
// ---------------------------------------------------------------------------
__global__ __launch_bounds__(256)
void concat3_kernel(const float* __restrict__ a, const float* __restrict__ b,
                    const float* __restrict__ c, float* __restrict__ out)
{
    int i = blockIdx.x * 256 + threadIdx.x;
    if (i < DMODEL)            out[i] = a[i];
    else if (i < 2 * DMODEL)   out[i] = b[i - DMODEL];
    else if (i < 3 * DMODEL)   out[i] = c[i - 2 * DMODEL];
}

// ---------------------------------------------------------------------------
// bf16 batched strided transpose: V strip of QKV [B][T][ld] -> [B][D][T]
// ---------------------------------------------------------------------------
__global__ __launch_bounds__(256)
void transb_kernel(const bf16* __restrict__ in, bf16* __restrict__ out, int ld)
{
    __shared__ bf16 t[32][33];
    const int bx = blockIdx.x, by = blockIdx.y, bz = blockIdx.z;  // bx: D/32, by: T/32
    const bf16* pi = in + (long long)bz * TSEQ * ld;
    bf16* po = out + (long long)bz * DMODEL * TSEQ;
    const int x = threadIdx.x & 31, y = threadIdx.x >> 5;
    #pragma unroll
    for (int i = 0; i < 4; i++)
        t[y + i * 8][x] = pi[(long long)(by * 32 + y + i * 8) * ld + bx * 32 + x];
    __syncthreads();
    #pragma unroll
    for (int i = 0; i < 4; i++)
        po[(long long)(bx * 32 + y + i * 8) * TSEQ + by * 32 + x] = t[x][y + i * 8];
}

// ---------------------------------------------------------------------------
// Causal softmax (row staged in smem): fp32 logits -> bf16 probs, zero tail
// ---------------------------------------------------------------------------
__global__ __launch_bounds__(256)
void softmax_causal_kernel(const float* __restrict__ S, bf16* __restrict__ P)
{
    __shared__ float buf[TSEQ];
    __shared__ float red[256];
    const int t = blockIdx.x, b = blockIdx.y;
    const float* row = S + ((long long)b * TSEQ + t) * TSEQ;
    bf16* prow = P + ((long long)b * TSEQ + t) * TSEQ;
    const int len = t + 1;
    const int tid = threadIdx.x;

    float m = -1e30f;
    for (int s = tid; s < len; s += 256) { float v = row[s]; buf[s] = v; m = fmaxf(m, v); }
    red[tid] = m; __syncthreads();
    for (int o = 128; o > 0; o >>= 1) {
        if (tid < o) red[tid] = fmaxf(red[tid], red[tid + o]);
        __syncthreads();
    }
    m = red[0];
    __syncthreads();

    float sum = 0.0f;
    for (int s = tid; s < len; s += 256) { float e = expf(buf[s] - m); buf[s] = e; sum += e; }
    red[tid] = sum; __syncthreads();
    for (int o = 128; o > 0; o >>= 1) {
        if (tid < o) red[tid] += red[tid + o];
        __syncthreads();
    }
    const float inv = 1.0f / red[0];

    for (int s = tid; s < len; s += 256)        prow[s] = __float2bfloat16_rn(buf[s] * inv);
    for (int s = len + tid; s < TSEQ; s += 256) prow[s] = __float2bfloat16_rn(0.0f);
}

// ---------------------------------------------------------------------------
// out = LayerNorm(Xa + Xb) * g + be ; optional bf16 copy
// ---------------------------------------------------------------------------
__global__ __launch_bounds__(256)
void add_ln_kernel(const float* __restrict__ Xa, const float* __restrict__ Xb,
                   const float* __restrict__ g,  const float* __restrict__ be,
                   float* __restrict__ out, bf16* __restrict__ out_bf)
{
    const int row = blockIdx.x;
    const int tid = threadIdx.x;
    const float* pa = Xa + (long long)row * DMODEL;
    const float* pb = Xb + (long long)row * DMODEL;

    float x[4];
    float s1 = 0.0f, s2 = 0.0f;
    #pragma unroll
    for (int i = 0; i < 4; i++) {
        int c = tid + i * 256;
        x[i] = pa[c] + pb[c];
        s1 += x[i];
        s2 += x[i] * x[i];
    }
    __shared__ float r1[256], r2[256];
    r1[tid] = s1; r2[tid] = s2; __syncthreads();
    for (int o = 128; o > 0; o >>= 1) {
        if (tid < o) { r1[tid] += r1[tid + o]; r2[tid] += r2[tid + o]; }
        __syncthreads();
    }
    const float mu  = r1[0] * (1.0f / DMODEL);
    const float var = r2[0] * (1.0f / DMODEL) - mu * mu;
    const float inv = rsqrtf(var + 1e-5f);

    float* po = out + (long long)row * DMODEL;
    #pragma unroll
    for (int i = 0; i < 4; i++) {
        int c = tid + i * 256;
        float v = (x[i] - mu) * inv * g[c] + be[c];
        po[c] = v;
        if (out_bf) out_bf[(long long)row * DMODEL + c] = __float2bfloat16_rn(v);
    }
}

// ---------------------------------------------------------------------------
// Host launch
// ---------------------------------------------------------------------------
extern "C" void kernel_launch(void* const* d_in, const int* in_sizes, int n_in,
                              void* d_out, int out_size)
{
    (void)in_sizes; (void)n_in; (void)out_size;
    const float* X   = (const float*)d_in[0];
    const float* WQ  = (const float*)d_in[1];
    const float* bQ  = (const float*)d_in[2];
    const float* WK  = (const float*)d_in[3];
    const float* bK  = (const float*)d_in[4];
    const float* WV  = (const float*)d_in[5];
    const float* bV  = (const float*)d_in[6];
    const float* WO  = (const float*)d_in[7];
    const float* bO  = (const float*)d_in[8];
    const float* W1  = (const float*)d_in[9];
    const float* b1  = (const float*)d_in[10];
    const float* W2  = (const float*)d_in[11];
    const float* b2  = (const float*)d_in[12];
    const float* g1  = (const float*)d_in[13];
    const float* be1 = (const float*)d_in[14];
    const float* g2  = (const float*)d_in[15];
    const float* be2 = (const float*)d_in[16];
    float* out = (float*)d_out;

    bf16 *Xb, *Wqkv, *WOt, *W1t, *W2t, *QKV, *VTb, *Pb, *AOb, *H1b, *FFb;
    float *bqkv, *S, *O, *H1, *H2;
    cudaGetSymbolAddress((void**)&Xb,   g_Xb);
    cudaGetSymbolAddress((void**)&Wqkv, g_Wqkv);
    cudaGetSymbolAddress((void**)&bqkv, g_bqkv);
    cudaGetSymbolAddress((void**)&WOt,  g_WOt);
    cudaGetSymbolAddress((void**)&W1t,  g_W1t);
    cudaGetSymbolAddress((void**)&W2t,  g_W2t);
    cudaGetSymbolAddress((void**)&QKV,  g_QKV);
    cudaGetSymbolAddress((void**)&VTb,  g_VTb);
    cudaGetSymbolAddress((void**)&Pb,   g_Pb);
    cudaGetSymbolAddress((void**)&AOb,  g_AOb);
    cudaGetSymbolAddress((void**)&H1b,  g_H1b);
    cudaGetSymbolAddress((void**)&FFb,  g_FFb);
    cudaGetSymbolAddress((void**)&S,    g_S);
    cudaGetSymbolAddress((void**)&O,    g_O);
    cudaGetSymbolAddress((void**)&H1,   g_H1);
    cudaGetSymbolAddress((void**)&H2,   g_H2);

    cudaFuncSetAttribute(bfgemm_kernel<1, true,  false, false>, cudaFuncAttributeMaxDynamicSharedMemorySize, GEMM_SMEM);
    cudaFuncSetAttribute(bfgemm_kernel<0, false, true,  false>, cudaFuncAttributeMaxDynamicSharedMemorySize, GEMM_SMEM);
    cudaFuncSetAttribute(bfgemm_kernel<0, true,  false, true >, cudaFuncAttributeMaxDynamicSharedMemorySize, GEMM_SMEM);
    cudaFuncSetAttribute(bfgemm_kernel<1, false, false, false>, cudaFuncAttributeMaxDynamicSharedMemorySize, GEMM_SMEM);
    cudaFuncSetAttribute(bfgemm_kernel<2, true,  false, false>, cudaFuncAttributeMaxDynamicSharedMemorySize, GEMM_SMEM);

    const dim3 blk256(256);

    // ---- convert / transpose inputs ----
    f2bf_kernel<<<NTOK * DMODEL / 1024, blk256>>>(X, Xb, NTOK * DMODEL);
    // weights transposed into the concatenated QKV weight [3072,1024]
    trans_f2bf_kernel<<<dim3(32, 32),  blk256>>>(WQ, Wqkv,                     DMODEL, DMODEL);
    trans_f2bf_kernel<<<dim3(32, 32),  blk256>>>(WK, Wqkv + DMODEL * DMODEL,   DMODEL, DMODEL);
    trans_f2bf_kernel<<<dim3(32, 32),  blk256>>>(WV, Wqkv + 2 * DMODEL * DMODEL, DMODEL, DMODEL);
    trans_f2bf_kernel<<<dim3(32, 32),  blk256>>>(WO, WOt, DMODEL, DMODEL);
    trans_f2bf_kernel<<<dim3(128, 32), blk256>>>(W1, W1t, DMODEL, DFF);   // -> [4096,1024]
    trans_f2bf_kernel<<<dim3(32, 128), blk256>>>(W2, W2t, DFF, DMODEL);   // -> [1024,4096]
    concat3_kernel<<<12, blk256>>>(bQ, bK, bV, bqkv);

    const dim3 gQKV(DQKV / 128, NTOK / 128);               // 24 x 64 = 1536
    const dim3 gProj(DMODEL / 128, NTOK / 128);            // 8 x 64
    const dim3 gS(TSEQ / 128, TSEQ / 128, NB);             // 16 x 16 x 4
    const dim3 gAV(DMODEL / 128, TSEQ / 128, NB);          // 8 x 16 x 4
    const dim3 gFF1(DFF / 128, NTOK / 128);                // 32 x 64

    const long long sQKV = (long long)TSEQ * DQKV;
    const long long sQK  = (long long)TSEQ * DMODEL;
    const long long sSS  = (long long)TSEQ * TSEQ;

    // fused QKV projection -> bf16 [8192, 3072]
    bfgemm_kernel<1, true, false, false><<<gQKV, blk256, GEMM_SMEM>>>(
        Xb, DMODEL, Wqkv, DMODEL, bqkv, QKV, NTOK, DQKV, DMODEL, 1.0f, 0, 0, 0);

    // V^T per batch for A@V (V strip = QKV cols [2048,3072))
    transb_kernel<<<dim3(DMODEL / 32, TSEQ / 32, NB), blk256>>>(QKV + 2 * DMODEL, VTb, DQKV);

    // scores = (Q @ K^T)/sqrt(D) -> fp32 (Q strip lda=3072, K strip ldb=3072)
    bfgemm_kernel<0, false, true, false><<<gS, blk256, GEMM_SMEM>>>(
        QKV, DQKV, QKV + DMODEL, DQKV, nullptr, S, TSEQ, TSEQ, DMODEL,
        0.03125f, sQKV, sQKV, sSS);

    // causal softmax -> bf16 probs
    softmax_causal_kernel<<<dim3(TSEQ, NB), blk256>>>(S, Pb);

    // attn = P @ V  (B = V^T [D,T]) -> bf16
    bfgemm_kernel<0, true, false, true><<<gAV, blk256, GEMM_SMEM>>>(
        Pb, TSEQ, VTb, TSEQ, nullptr, AOb, TSEQ, DMODEL, TSEQ,
        1.0f, sSS, (long long)DMODEL * TSEQ, sQK);

    // O projection -> fp32
    bfgemm_kernel<1, false, false, false><<<gProj, blk256, GEMM_SMEM>>>(
        AOb, DMODEL, WOt, DMODEL, bO, O, NTOK, DMODEL, DMODEL, 1.0f, 0, 0, 0);

    // H1 = LN(O + X)
    add_ln_kernel<<<NTOK, blk256>>>(O, X, g1, be1, H1, H1b);

    // FF = gelu(H1 @ W1 + b1) -> bf16
    bfgemm_kernel<2, true, false, false><<<gFF1, blk256, GEMM_SMEM>>>(
        H1b, DMODEL, W1t, DMODEL, b1, FFb, NTOK, DFF, DMODEL, 1.0f, 0, 0, 0);

    // H2 = FF @ W2 + b2 -> fp32
    bfgemm_kernel<1, false, false, false><<<gProj, blk256, GEMM_SMEM>>>(
        FFb, DFF, W2t, DFF, b2, H2, NTOK, DMODEL, DFF, 1.0f, 0, 0, 0);

    // out = LN(H2 + H1)
    add_ln_kernel<<<NTOK, blk256>>>(H2, H1, g2, be2, out, nullptr);
}

// round 15
// speedup vs baseline: 1.2243x; 1.0014x over previous
#include <cuda_runtime.h>
#include <cuda_bf16.h>
#include <mma.h>
#include <math.h>
#include <stdint.h>

using namespace nvcuda;

// Problem constants
#define NB     4
#define TSEQ   2048
#define DMODEL 1024
#define DFF    4096
#define NTOK   (NB * TSEQ)   // 8192
#define DQKV   3072          // fused QKV width

typedef __nv_bfloat16 bf16;

// ---------------------------------------------------------------------------
// Scratch (device globals — no allocations allowed)
// ---------------------------------------------------------------------------
__device__ bf16  g_Xb  [NTOK * DMODEL];
__device__ bf16  g_Wqkv[DQKV * DMODEL];              // concat [3072,1024] [N,K]
__device__ float g_bqkv[DQKV];
__device__ bf16  g_WOt [DMODEL * DMODEL];
__device__ bf16  g_W1t [DFF * DMODEL];               // [4096,1024]
__device__ bf16  g_W2t [DMODEL * DFF];               // [1024,4096]
__device__ bf16  g_QKV [(size_t)NTOK * DQKV];        // fused Q|K|V rows
__device__ bf16  g_VTb [(size_t)NB * DMODEL * TSEQ]; // V^T per batch [D,T]
__device__ bf16  g_Pb  [(size_t)NB * TSEQ * TSEQ];   // probs bf16
__device__ bf16  g_AOb [NTOK * DMODEL];
__device__ bf16  g_H1b [NTOK * DMODEL];
__device__ bf16  g_FFb [(size_t)NTOK * DFF];
__device__ float g_S   [(size_t)NB * TSEQ * TSEQ];   // fp32 logits
__device__ float g_O   [NTOK * DMODEL];
__device__ float g_H1  [NTOK * DMODEL];
__device__ float g_H2  [NTOK * DMODEL];

// ---------------------------------------------------------------------------
// PTX helpers
// ---------------------------------------------------------------------------
__device__ __forceinline__ uint32_t smem_u32(const void* p) {
    return (uint32_t)__cvta_generic_to_shared(p);
}
__device__ __forceinline__ void mbar_init(uint32_t addr, uint32_t count) {
    asm volatile("mbarrier.init.shared.b64 [%0], %1;" :: "r"(addr), "r"(count) : "memory");
}
__device__ __forceinline__ void mbar_arrive_expect(uint32_t addr, uint32_t bytes) {
    asm volatile("mbarrier.arrive.expect_tx.shared.b64 _, [%0], %1;"
                 :: "r"(addr), "r"(bytes) : "memory");
}
__device__ __forceinline__ void mbar_wait(uint32_t addr, uint32_t parity) {
    asm volatile(
        "{\n\t.reg .pred P;\n"
        "WAIT_%=:\n\t"
        "mbarrier.try_wait.parity.acquire.cta.shared::cta.b64 P, [%0], %1;\n\t"
        "@!P bra WAIT_%=;\n\t}"
        :: "r"(addr), "r"(parity) : "memory");
}
__device__ __forceinline__ void bulk_g2s(uint32_t dst, const void* src,
                                         uint32_t bytes, uint32_t mbar) {
    asm volatile(
        "cp.async.bulk.shared::cluster.global.mbarrier::complete_tx::bytes [%0], [%1], %2, [%3];"
        :: "r"(dst), "l"(src), "r"(bytes), "r"(mbar) : "memory");
}

// ---------------------------------------------------------------------------
// bf16 tensor-core GEMM: C = alpha * A @ B^T [+bias][gelu]   (R10 core)
// Block tile 128x128, BK=64, 3-stage cp.async.bulk + mbarrier pipeline.
// 256 threads, 8 warps (2M x 4N, warp tile 64x32), 2 CTAs/SM. lda/ldb views.
// Epilogue: bf16 outputs (OUTB) go through smem staging (position-dependent
// pack); fp32 outputs store fragments DIRECTLY to global, with bias applied
// layout-agnostically via an accumulator fragment loaded from a 16x128 smem
// tile of replicated bias rows.
//   EPI: 0=none, 1=+bias, 2=+bias+GELU (GELU only with OUTB staging path)
//   CSKIP: skip tiles above diagonal ; CK: clamp K to (by+1)*128
// ---------------------------------------------------------------------------
template <int EPI, bool OUTB, bool CSKIP, bool CK>
__global__ __launch_bounds__(256, 2)
void bfgemm_kernel(const bf16* __restrict__ A, int lda,
                   const bf16* __restrict__ B, int ldb,
                   const float* __restrict__ bias, void* __restrict__ Cv,
                   int M, int N, int K, float alpha,
                   long long sA, long long sB, long long sC)
{
    constexpr int BK = 64;
    constexpr int ASTB = 144;                     // smem row stride, bytes
    constexpr int AST  = 72;                      // bf16 elems (mult of 8)
    constexpr int OP_B = 128 * ASTB;              // 18432 B per operand
    constexpr int STAGE_B = 2 * OP_B;             // 36864 B per stage

    const int bx = blockIdx.x, by = blockIdx.y, bz = blockIdx.z;
    if (CSKIP && bx > by) return;

    A += (long long)bz * sA;
    B += (long long)bz * sB;

    const int m0 = by * 128, n0 = bx * 128;
    const int kEnd = CK ? min(K, (by + 1) * 128) : K;
    const int nIter = kEnd / BK;

    extern __shared__ __align__(16) char smem_raw[];
    const uint32_t smemBase = smem_u32(smem_raw);
    const uint32_t tile0 = (smemBase + 1023) & ~1023u;

    __shared__ __align__(8) uint64_t s_mbar[3];
    const int tid = threadIdx.x;
    const int wid = tid >> 5;
    const int wy = wid >> 2;                      // 0..1 -> M (64 rows)
    const int wx = wid & 3;                       // 0..3 -> N (32 cols)

    if (tid == 0) {
        mbar_init(smem_u32(&s_mbar[0]), 256);
        mbar_init(smem_u32(&s_mbar[1]), 256);
        mbar_init(smem_u32(&s_mbar[2]), 256);
    }
    __syncthreads();
    const uint32_t mb0 = smem_u32(&s_mbar[0]);

    // each thread owns one 128B row copy per stage
    const bool isA = tid < 128;
    const int rrow = isA ? tid : tid - 128;
    const bf16* gbase = isA ? (A + (long long)(m0 + rrow) * lda)
                            : (B + (long long)(n0 + rrow) * ldb);
    const uint32_t sOff = (isA ? 0u : (uint32_t)OP_B) + (uint32_t)rrow * ASTB;

    auto load_stage = [&](int it, int s) {
        const uint32_t mb = mb0 + s * 8;
        mbar_arrive_expect(mb, 128);              // own expect precedes own copy
        bulk_g2s(tile0 + (uint32_t)s * STAGE_B + sOff,
                 gbase + (long long)it * BK, 128, mb);
    };

    wmma::fragment<wmma::accumulator, 16, 16, 16, float> c_frag[4][2];
    #pragma unroll
    for (int i = 0; i < 4; i++)
        #pragma unroll
        for (int j = 0; j < 2; j++)
            wmma::fill_fragment(c_frag[i][j], 0.0f);

    // ---- prologue: 2 stages in flight ----
    load_stage(0, 0);
    if (nIter > 1) load_stage(1, 1);

    uint32_t ph[3] = {0, 0, 0};

    for (int it = 0; it < nIter; it++) {
        const int s = it % 3;
        mbar_wait(mb0 + s * 8, ph[s]);
        ph[s] ^= 1;

        if (it + 2 < nIter) load_stage(it + 2, (it + 2) % 3);

        const bf16* As = (const bf16*)(smem_raw + (tile0 - smemBase) + s * STAGE_B);
        const bf16* Bs = (const bf16*)((const char*)As + OP_B);

        #pragma unroll
        for (int kk = 0; kk < BK; kk += 16) {
            wmma::fragment<wmma::matrix_a, 16, 16, 16, bf16, wmma::row_major> a_frag[4];
            wmma::fragment<wmma::matrix_b, 16, 16, 16, bf16, wmma::col_major> b_frag[2];
            #pragma unroll
            for (int i = 0; i < 4; i++)
                wmma::load_matrix_sync(a_frag[i], &As[(wy * 64 + i * 16) * AST + kk], AST);
            #pragma unroll
            for (int j = 0; j < 2; j++)
                wmma::load_matrix_sync(b_frag[j], &Bs[(wx * 32 + j * 16) * AST + kk], AST);
            #pragma unroll
            for (int i = 0; i < 4; i++)
                #pragma unroll
                for (int j = 0; j < 2; j++)
                    wmma::mma_sync(c_frag[i][j], a_frag[i], b_frag[j], c_frag[i][j]);
        }
        __syncthreads();
    }

    if (!OUTB) {
        // ---- DIRECT epilogue: fp32 out; alpha + bias fragment-wise ----
        float* Cf = (float*)Cv + (long long)bz * sC;
        wmma::fragment<wmma::accumulator, 16, 16, 16, float> bias_frag[2];
        if (EPI >= 1) {
            float* bt = (float*)smem_raw;         // 16 x 128 replicated bias rows
            #pragma unroll
            for (int i = 0; i < 8; i++) {
                int f = tid + i * 256;
                bt[f] = bias[n0 + (f & 127)];
            }
            __syncthreads();
            #pragma unroll
            for (int j = 0; j < 2; j++)
                wmma::load_matrix_sync(bias_frag[j], bt + wx * 32 + j * 16, 128,
                                       wmma::mem_row_major);
        }
        #pragma unroll
        for (int i = 0; i < 4; i++)
            #pragma unroll
            for (int j = 0; j < 2; j++) {
                #pragma unroll
                for (int e = 0; e < c_frag[i][j].num_elements; e++) {
                    float x = c_frag[i][j].x[e] * alpha;
                    if (EPI >= 1) x += bias_frag[j].x[e];
                    c_frag[i][j].x[e] = x;
                }
                wmma::store_matrix_sync(
                    Cf + (long long)(m0 + wy * 64 + i * 16) * N + n0 + wx * 32 + j * 16,
                    c_frag[i][j], N, wmma::mem_row_major);
            }
    } else {
        // ---- staging epilogue: bf16 out (position-dependent pack / GELU) ----
        constexpr int STG = 136;
        float* Stage = (float*)smem_raw;
        #pragma unroll
        for (int p = 0; p < 2; p++) {
            if (wy == p) {
                #pragma unroll
                for (int i = 0; i < 4; i++)
                    #pragma unroll
                    for (int j = 0; j < 2; j++)
                        wmma::store_matrix_sync(&Stage[(i * 16) * STG + wx * 32 + j * 16],
                                                c_frag[i][j], STG, wmma::mem_row_major);
            }
            __syncthreads();
            #pragma unroll
            for (int i = 0; i < 8; i++) {
                int f = tid + i * 256;            // 2048 float4 over 64x128
                int r = f >> 5, c4 = f & 31;
                float4 v = *(const float4*)&Stage[r * STG + c4 * 4];
                float o[4] = {v.x, v.y, v.z, v.w};
                #pragma unroll
                for (int e = 0; e < 4; e++) {
                    float x = o[e] * alpha;
                    if (EPI >= 1) x += bias[n0 + c4 * 4 + e];
                    if (EPI == 2) x = 0.5f * x * (1.0f + erff(x * 0.70710678118654752f));
                    o[e] = x;
                }
                const long long off = (long long)bz * sC + (long long)(m0 + p * 64 + r) * N + n0 + c4 * 4;
                ushort4 u;
                u.x = __bfloat16_as_ushort(__float2bfloat16_rn(o[0]));
                u.y = __bfloat16_as_ushort(__float2bfloat16_rn(o[1]));
                u.z = __bfloat16_as_ushort(__float2bfloat16_rn(o[2]));
                u.w = __bfloat16_as_ushort(__float2bfloat16_rn(o[3]));
                *(ushort4*)((bf16*)Cv + off) = u;
            }
            __syncthreads();
        }
    }
}

static const int GEMM_SMEM = 1024 + 3 * 36864;    // 111616 B -> 2 CTAs/SM

// ---------------------------------------------------------------------------
// fp32 -> bf16
// ---------------------------------------------------------------------------
__global__ __launch_bounds__(256)
void f2bf_kernel(const float* __restrict__ in, bf16* __restrict__ out, int n)
{
    int i = (blockIdx.x * 256 + threadIdx.x) * 4;
    if (i >= n) return;
    float4 v = *(const float4*)(in + i);
    ushort4 o;
    o.x = __bfloat16_as_ushort(__float2bfloat16_rn(v.x));
    o.y = __bfloat16_as_ushort(__float2bfloat16_rn(v.y));
    o.z = __bfloat16_as_ushort(__float2bfloat16_rn(v.z));
    o.w = __bfloat16_as_ushort(__float2bfloat16_rn(v.w));
    *(ushort4*)(out + i) = o;
}

// ---------------------------------------------------------------------------
// fp32 [R,C] -> bf16 [C,R]
// ---------------------------------------------------------------------------
__global__ __launch_bounds__(256)
void trans_f2bf_kernel(const float* __restrict__ in, bf16* __restrict__ out, int R, int C)
{
    __shared__ float t[32][33];
    const int bx = blockIdx.x, by = blockIdx.y;
    const int x = threadIdx.x & 31, y = threadIdx.x >> 5;
    #pragma unroll
    for (int i = 0; i < 4; i++) {
        int r = by * 32 + y + i * 8;
        t[y + i * 8][x] = in[(long long)r * C + bx * 32 + x];
    }
    __syncthreads();
    #pragma unroll
    for (int i = 0; i < 4; i++) {
        int cc = bx * 32 + y + i * 8;
        int rr = by * 32 + x;
        out[(long long)cc * R + rr] = __float2bfloat16_rn(t[x][y + i * 8]);
    }
}

// ---------------------------------------------------------------------------
// concat 3 fp32 vectors of DMODEL into one [3072]
// ---------------------------------------------------------------------------
__global__ __launch_bounds__(256)
void concat3_kernel(const float* __restrict__ a, const float* __restrict__ b,
                    const float* __restrict__ c, float* __restrict__ out)
{
    int i = blockIdx.x * 256 + threadIdx.x;
    if (i < DMODEL)            out[i] = a[i];
    else if (i < 2 * DMODEL)   out[i] = b[i - DMODEL];
    else if (i < 3 * DMODEL)   out[i] = c[i - 2 * DMODEL];
}

// ---------------------------------------------------------------------------
// bf16 batched strided transpose: V strip of QKV [B][T][ld] -> [B][D][T]
// ---------------------------------------------------------------------------
__global__ __launch_bounds__(256)
void transb_kernel(const bf16* __restrict__ in, bf16* __restrict__ out, int ld)
{
    __shared__ bf16 t[32][33];
    const int bx = blockIdx.x, by = blockIdx.y, bz = blockIdx.z;
    const bf16* pi = in + (long long)bz * TSEQ * ld;
    bf16* po = out + (long long)bz * DMODEL * TSEQ;
    const int x = threadIdx.x & 31, y = threadIdx.x >> 5;
    #pragma unroll
    for (int i = 0; i < 4; i++)
        t[y + i * 8][x] = pi[(long long)(by * 32 + y + i * 8) * ld + bx * 32 + x];
    __syncthreads();
    #pragma unroll
    for (int i = 0; i < 4; i++)
        po[(long long)(bx * 32 + y + i * 8) * TSEQ + by * 32 + x] = t[x][y + i * 8];
}

// ---------------------------------------------------------------------------
// Causal softmax: fp32 logits -> bf16 probs; zero tail only to the 128-
// boundary that A@V's causal K-clamp actually reads.
// ---------------------------------------------------------------------------
__global__ __launch_bounds__(256)
void softmax_causal_kernel(const float* __restrict__ S, bf16* __restrict__ P)
{
    __shared__ float buf[TSEQ];
    __shared__ float red[256];
    const int t = blockIdx.x, b = blockIdx.y;
    const float* row = S + ((long long)b * TSEQ + t) * TSEQ;
    bf16* prow = P + ((long long)b * TSEQ + t) * TSEQ;
    const int len = t + 1;
    const int zEnd = ((t >> 7) + 1) << 7;         // next 128 boundary
    const int tid = threadIdx.x;

    float m = -1e30f;
    for (int s = tid; s < len; s += 256) { float v = row[s]; buf[s] = v; m = fmaxf(m, v); }
    red[tid] = m; __syncthreads();
    for (int o = 128; o > 0; o >>= 1) {
        if (tid < o) red[tid] = fmaxf(red[tid], red[tid + o]);
        __syncthreads();
    }
    m = red[0];
    __syncthreads();

    float sum = 0.0f;
    for (int s = tid; s < len; s += 256) { float e = expf(buf[s] - m); buf[s] = e; sum += e; }
    red[tid] = sum; __syncthreads();
    for (int o = 128; o > 0; o >>= 1) {
        if (tid < o) red[tid] += red[tid + o];
        __syncthreads();
    }
    const float inv = 1.0f / red[0];

    for (int s = tid; s < len; s += 256)        prow[s] = __float2bfloat16_rn(buf[s] * inv);
    for (int s = len + tid; s < zEnd; s += 256) prow[s] = __float2bfloat16_rn(0.0f);
}

// ---------------------------------------------------------------------------
// out = LayerNorm(Xa + Xb) * g + be ; optional bf16 copy
// ---------------------------------------------------------------------------
__global__ __launch_bounds__(256)
void add_ln_kernel(const float* __restrict__ Xa, const float* __restrict__ Xb,
                   const float* __restrict__ g,  const float* __restrict__ be,
                   float* __restrict__ out, bf16* __restrict__ out_bf)
{
    const int row = blockIdx.x;
    const int tid = threadIdx.x;
    const float* pa = Xa + (long long)row * DMODEL;
    const float* pb = Xb + (long long)row * DMODEL;

    float x[4];
    float s1 = 0.0f, s2 = 0.0f;
    #pragma unroll
    for (int i = 0; i < 4; i++) {
        int c = tid + i * 256;
        x[i] = pa[c] + pb[c];
        s1 += x[i];
        s2 += x[i] * x[i];
    }
    __shared__ float r1[256], r2[256];
    r1[tid] = s1; r2[tid] = s2; __syncthreads();
    for (int o = 128; o > 0; o >>= 1) {
        if (tid < o) { r1[tid] += r1[tid + o]; r2[tid] += r2[tid + o]; }
        __syncthreads();
    }
    const float mu  = r1[0] * (1.0f / DMODEL);
    const float var = r2[0] * (1.0f / DMODEL) - mu * mu;
    const float inv = rsqrtf(var + 1e-5f);

    float* po = out + (long long)row * DMODEL;
    #pragma unroll
    for (int i = 0; i < 4; i++) {
        int c = tid + i * 256;
        float v = (x[i] - mu) * inv * g[c] + be[c];
        po[c] = v;
        if (out_bf) out_bf[(long long)row * DMODEL + c] = __float2bfloat16_rn(v);
    }
}

// ---------------------------------------------------------------------------
// Host launch
// ---------------------------------------------------------------------------
extern "C" void kernel_launch(void* const* d_in, const int* in_sizes, int n_in,
                              void* d_out, int out_size)
{
    (void)in_sizes; (void)n_in; (void)out_size;
    const float* X   = (const float*)d_in[0];
    const float* WQ  = (const float*)d_in[1];
    const float* bQ  = (const float*)d_in[2];
    const float* WK  = (const float*)d_in[3];
    const float* bK  = (const float*)d_in[4];
    const float* WV  = (const float*)d_in[5];
    const float* bV  = (const float*)d_in[6];
    const float* WO  = (const float*)d_in[7];
    const float* bO  = (const float*)d_in[8];
    const float* W1  = (const float*)d_in[9];
    const float* b1  = (const float*)d_in[10];
    const float* W2  = (const float*)d_in[11];
    const float* b2  = (const float*)d_in[12];
    const float* g1  = (const float*)d_in[13];
    const float* be1 = (const float*)d_in[14];
    const float* g2  = (const float*)d_in[15];
    const float* be2 = (const float*)d_in[16];
    float* out = (float*)d_out;

    bf16 *Xb, *Wqkv, *WOt, *W1t, *W2t, *QKV, *VTb, *Pb, *AOb, *H1b, *FFb;
    float *bqkv, *S, *O, *H1, *H2;
    cudaGetSymbolAddress((void**)&Xb,   g_Xb);
    cudaGetSymbolAddress((void**)&Wqkv, g_Wqkv);
    cudaGetSymbolAddress((void**)&bqkv, g_bqkv);
    cudaGetSymbolAddress((void**)&WOt,  g_WOt);
    cudaGetSymbolAddress((void**)&W1t,  g_W1t);
    cudaGetSymbolAddress((void**)&W2t,  g_W2t);
    cudaGetSymbolAddress((void**)&QKV,  g_QKV);
    cudaGetSymbolAddress((void**)&VTb,  g_VTb);
    cudaGetSymbolAddress((void**)&Pb,   g_Pb);
    cudaGetSymbolAddress((void**)&AOb,  g_AOb);
    cudaGetSymbolAddress((void**)&H1b,  g_H1b);
    cudaGetSymbolAddress((void**)&FFb,  g_FFb);
    cudaGetSymbolAddress((void**)&S,    g_S);
    cudaGetSymbolAddress((void**)&O,    g_O);
    cudaGetSymbolAddress((void**)&H1,   g_H1);
    cudaGetSymbolAddress((void**)&H2,   g_H2);

    cudaFuncSetAttribute(bfgemm_kernel<1, true,  false, false>, cudaFuncAttributeMaxDynamicSharedMemorySize, GEMM_SMEM);
    cudaFuncSetAttribute(bfgemm_kernel<0, false, true,  false>, cudaFuncAttributeMaxDynamicSharedMemorySize, GEMM_SMEM);
    cudaFuncSetAttribute(bfgemm_kernel<0, true,  false, true >, cudaFuncAttributeMaxDynamicSharedMemorySize, GEMM_SMEM);
    cudaFuncSetAttribute(bfgemm_kernel<1, false, false, false>, cudaFuncAttributeMaxDynamicSharedMemorySize, GEMM_SMEM);
    cudaFuncSetAttribute(bfgemm_kernel<2, true,  false, false>, cudaFuncAttributeMaxDynamicSharedMemorySize, GEMM_SMEM);

    const dim3 blk256(256);

    // ---- convert / transpose inputs ----
    f2bf_kernel<<<NTOK * DMODEL / 1024, blk256>>>(X, Xb, NTOK * DMODEL);
    trans_f2bf_kernel<<<dim3(32, 32),  blk256>>>(WQ, Wqkv,                       DMODEL, DMODEL);
    trans_f2bf_kernel<<<dim3(32, 32),  blk256>>>(WK, Wqkv + DMODEL * DMODEL,     DMODEL, DMODEL);
    trans_f2bf_kernel<<<dim3(32, 32),  blk256>>>(WV, Wqkv + 2 * DMODEL * DMODEL, DMODEL, DMODEL);
    trans_f2bf_kernel<<<dim3(32, 32),  blk256>>>(WO, WOt, DMODEL, DMODEL);
    trans_f2bf_kernel<<<dim3(128, 32), blk256>>>(W1, W1t, DMODEL, DFF);   // -> [4096,1024]
    trans_f2bf_kernel<<<dim3(32, 128), blk256>>>(W2, W2t, DFF, DMODEL);   // -> [1024,4096]
    concat3_kernel<<<12, blk256>>>(bQ, bK, bV, bqkv);

    const dim3 gQKV(DQKV / 128, NTOK / 128);               // 24 x 64
    const dim3 gProj(DMODEL / 128, NTOK / 128);            // 8 x 64
    const dim3 gS(TSEQ / 128, TSEQ / 128, NB);             // 16 x 16 x 4
    const dim3 gAV(DMODEL / 128, TSEQ / 128, NB);          // 8 x 16 x 4
    const dim3 gFF1(DFF / 128, NTOK / 128);                // 32 x 64

    const long long sQKV = (long long)TSEQ * DQKV;
    const long long sQK  = (long long)TSEQ * DMODEL;
    const long long sSS  = (long long)TSEQ * TSEQ;

    // fused QKV projection -> bf16 [8192, 3072]  (staging epilogue)
    bfgemm_kernel<1, true, false, false><<<gQKV, blk256, GEMM_SMEM>>>(
        Xb, DMODEL, Wqkv, DMODEL, bqkv, QKV, NTOK, DQKV, DMODEL, 1.0f, 0, 0, 0);

    // V^T per batch for A@V (V strip = QKV cols [2048,3072))
    transb_kernel<<<dim3(DMODEL / 32, TSEQ / 32, NB), blk256>>>(QKV + 2 * DMODEL, VTb, DQKV);

    // scores = (Q @ K^T)/sqrt(D) -> fp32  (DIRECT epilogue)
    bfgemm_kernel<0, false, true, false><<<gS, blk256, GEMM_SMEM>>>(
        QKV, DQKV, QKV + DMODEL, DQKV, nullptr, S, TSEQ, TSEQ, DMODEL,
        0.03125f, sQKV, sQKV, sSS);

    // causal softmax -> bf16 probs
    softmax_causal_kernel<<<dim3(TSEQ, NB), blk256>>>(S, Pb);

    // attn = P @ V  (B = V^T [D,T]) -> bf16 (staging epilogue)
    bfgemm_kernel<0, true, false, true><<<gAV, blk256, GEMM_SMEM>>>(
        Pb, TSEQ, VTb, TSEQ, nullptr, AOb, TSEQ, DMODEL, TSEQ,
        1.0f, sSS, (long long)DMODEL * TSEQ, sQK);

    // O projection -> fp32 (DIRECT epilogue, bias fragment)
    bfgemm_kernel<1, false, false, false><<<gProj, blk256, GEMM_SMEM>>>(
        AOb, DMODEL, WOt, DMODEL, bO, O, NTOK, DMODEL, DMODEL, 1.0f, 0, 0, 0);

    // H1 = LN(O + X)
    add_ln_kernel<<<NTOK, blk256>>>(O, X, g1, be1, H1, H1b);

    // FF = gelu(H1 @ W1 + b1) -> bf16 (staging epilogue)
    bfgemm_kernel<2, true, false, false><<<gFF1, blk256, GEMM_SMEM>>>(
        H1b, DMODEL, W1t, DMODEL, b1, FFb, NTOK, DFF, DMODEL, 1.0f, 0, 0, 0);

    // H2 = FF @ W2 + b2 -> fp32 (DIRECT epilogue, bias fragment)
    bfgemm_kernel<1, false, false, false><<<gProj, blk256, GEMM_SMEM>>>(
        FFb, DFF, W2t, DFF, b2, H2, NTOK, DMODEL, DFF, 1.0f, 0, 0, 0);

    // out = LN(H2 + H1)
    add_ln_kernel<<<NTOK, blk256>>>(H2, H1, g2, be2, out, nullptr);
}

// round 16
// speedup vs baseline: 1.2286x; 1.0035x over previous
#include <cuda_runtime.h>
#include <cuda_bf16.h>
#include <mma.h>
#include <math.h>
#include <stdint.h>

using namespace nvcuda;

// Problem constants
#define NB     4
#define TSEQ   2048
#define DMODEL 1024
#define DFF    4096
#define NTOK   (NB * TSEQ)   // 8192
#define DQKV   3072          // fused QKV width

typedef __nv_bfloat16 bf16;

// ---------------------------------------------------------------------------
// Scratch (device globals — no allocations allowed)
// ---------------------------------------------------------------------------
__device__ bf16  g_Xb  [NTOK * DMODEL];
__device__ bf16  g_Wqkv[DQKV * DMODEL];              // concat [3072,1024] [N,K]
__device__ float g_bqkv[DQKV];
__device__ bf16  g_WOt [DMODEL * DMODEL];
__device__ bf16  g_W1t [DFF * DMODEL];               // [4096,1024]
__device__ bf16  g_W2t [DMODEL * DFF];               // [1024,4096]
__device__ bf16  g_QKV [(size_t)NTOK * DQKV];        // fused Q|K|V rows
__device__ bf16  g_VTb [(size_t)NB * DMODEL * TSEQ]; // V^T per batch [D,T]
__device__ bf16  g_Pb  [(size_t)NB * TSEQ * TSEQ];   // probs bf16
__device__ bf16  g_AOb [NTOK * DMODEL];
__device__ bf16  g_H1b [NTOK * DMODEL];
__device__ bf16  g_FFb [(size_t)NTOK * DFF];
__device__ float g_S   [(size_t)NB * TSEQ * TSEQ];   // fp32 logits
__device__ float g_O   [NTOK * DMODEL];
__device__ float g_H1  [NTOK * DMODEL];
__device__ float g_H2  [NTOK * DMODEL];

// ---------------------------------------------------------------------------
// PTX helpers
// ---------------------------------------------------------------------------
__device__ __forceinline__ uint32_t smem_u32(const void* p) {
    return (uint32_t)__cvta_generic_to_shared(p);
}
__device__ __forceinline__ void mbar_init(uint32_t addr, uint32_t count) {
    asm volatile("mbarrier.init.shared.b64 [%0], %1;" :: "r"(addr), "r"(count) : "memory");
}
__device__ __forceinline__ void mbar_arrive_expect(uint32_t addr, uint32_t bytes) {
    asm volatile("mbarrier.arrive.expect_tx.shared.b64 _, [%0], %1;"
                 :: "r"(addr), "r"(bytes) : "memory");
}
__device__ __forceinline__ void mbar_wait(uint32_t addr, uint32_t parity) {
    asm volatile(
        "{\n\t.reg .pred P;\n"
        "WAIT_%=:\n\t"
        "mbarrier.try_wait.parity.acquire.cta.shared::cta.b64 P, [%0], %1;\n\t"
        "@!P bra WAIT_%=;\n\t}"
        :: "r"(addr), "r"(parity) : "memory");
}
__device__ __forceinline__ void bulk_g2s(uint32_t dst, const void* src,
                                         uint32_t bytes, uint32_t mbar) {
    asm volatile(
        "cp.async.bulk.shared::cluster.global.mbarrier::complete_tx::bytes [%0], [%1], %2, [%3];"
        :: "r"(dst), "l"(src), "r"(bytes), "r"(mbar) : "memory");
}

// ---------------------------------------------------------------------------
// bf16 tensor-core GEMM: C = alpha * A @ B^T [+bias][gelu]   (R10 core)
// Block tile 128x128, BK=64, 3-stage cp.async.bulk + mbarrier pipeline.
// 256 threads, 8 warps (2M x 4N, warp tile 64x32), 2 CTAs/SM. lda/ldb views.
//   EPI: 0=none, 1=+bias, 2=+bias+GELU ; OUTB: bf16 out (else fp32 direct)
//   CSKIP: skip tiles above diagonal ; CK: clamp K to (by+1)*128
// ---------------------------------------------------------------------------
template <int EPI, bool OUTB, bool CSKIP, bool CK>
__global__ __launch_bounds__(256, 2)
void bfgemm_kernel(const bf16* __restrict__ A, int lda,
                   const bf16* __restrict__ B, int ldb,
                   const float* __restrict__ bias, void* __restrict__ Cv,
                   int M, int N, int K, float alpha,
                   long long sA, long long sB, long long sC)
{
    constexpr int BK = 64;
    constexpr int ASTB = 144;                     // smem row stride, bytes
    constexpr int AST  = 72;                      // bf16 elems (mult of 8)
    constexpr int OP_B = 128 * ASTB;              // 18432 B per operand
    constexpr int STAGE_B = 2 * OP_B;             // 36864 B per stage

    const int bx = blockIdx.x, by = blockIdx.y, bz = blockIdx.z;
    if (CSKIP && bx > by) return;

    A += (long long)bz * sA;
    B += (long long)bz * sB;

    const int m0 = by * 128, n0 = bx * 128;
    const int kEnd = CK ? min(K, (by + 1) * 128) : K;
    const int nIter = kEnd / BK;

    extern __shared__ __align__(16) char smem_raw[];
    const uint32_t smemBase = smem_u32(smem_raw);
    const uint32_t tile0 = (smemBase + 1023) & ~1023u;

    __shared__ __align__(8) uint64_t s_mbar[3];
    const int tid = threadIdx.x;
    const int wid = tid >> 5;
    const int wy = wid >> 2;                      // 0..1 -> M (64 rows)
    const int wx = wid & 3;                       // 0..3 -> N (32 cols)

    if (tid == 0) {
        mbar_init(smem_u32(&s_mbar[0]), 256);
        mbar_init(smem_u32(&s_mbar[1]), 256);
        mbar_init(smem_u32(&s_mbar[2]), 256);
    }
    __syncthreads();
    const uint32_t mb0 = smem_u32(&s_mbar[0]);

    // each thread owns one 128B row copy per stage
    const bool isA = tid < 128;
    const int rrow = isA ? tid : tid - 128;
    const bf16* gbase = isA ? (A + (long long)(m0 + rrow) * lda)
                            : (B + (long long)(n0 + rrow) * ldb);
    const uint32_t sOff = (isA ? 0u : (uint32_t)OP_B) + (uint32_t)rrow * ASTB;

    auto load_stage = [&](int it, int s) {
        const uint32_t mb = mb0 + s * 8;
        mbar_arrive_expect(mb, 128);              // own expect precedes own copy
        bulk_g2s(tile0 + (uint32_t)s * STAGE_B + sOff,
                 gbase + (long long)it * BK, 128, mb);
    };

    wmma::fragment<wmma::accumulator, 16, 16, 16, float> c_frag[4][2];
    #pragma unroll
    for (int i = 0; i < 4; i++)
        #pragma unroll
        for (int j = 0; j < 2; j++)
            wmma::fill_fragment(c_frag[i][j], 0.0f);

    // ---- prologue: 2 stages in flight ----
    load_stage(0, 0);
    if (nIter > 1) load_stage(1, 1);

    uint32_t ph[3] = {0, 0, 0};

    for (int it = 0; it < nIter; it++) {
        const int s = it % 3;
        mbar_wait(mb0 + s * 8, ph[s]);
        ph[s] ^= 1;

        if (it + 2 < nIter) load_stage(it + 2, (it + 2) % 3);

        const bf16* As = (const bf16*)(smem_raw + (tile0 - smemBase) + s * STAGE_B);
        const bf16* Bs = (const bf16*)((const char*)As + OP_B);

        #pragma unroll
        for (int kk = 0; kk < BK; kk += 16) {
            wmma::fragment<wmma::matrix_a, 16, 16, 16, bf16, wmma::row_major> a_frag[4];
            wmma::fragment<wmma::matrix_b, 16, 16, 16, bf16, wmma::col_major> b_frag[2];
            #pragma unroll
            for (int i = 0; i < 4; i++)
                wmma::load_matrix_sync(a_frag[i], &As[(wy * 64 + i * 16) * AST + kk], AST);
            #pragma unroll
            for (int j = 0; j < 2; j++)
                wmma::load_matrix_sync(b_frag[j], &Bs[(wx * 32 + j * 16) * AST + kk], AST);
            #pragma unroll
            for (int i = 0; i < 4; i++)
                #pragma unroll
                for (int j = 0; j < 2; j++)
                    wmma::mma_sync(c_frag[i][j], a_frag[i], b_frag[j], c_frag[i][j]);
        }
        __syncthreads();
    }

    if (!OUTB) {
        // ---- DIRECT epilogue: fp32 out; alpha + bias fragment-wise ----
        float* Cf = (float*)Cv + (long long)bz * sC;
        wmma::fragment<wmma::accumulator, 16, 16, 16, float> bias_frag[2];
        if (EPI >= 1) {
            float* bt = (float*)smem_raw;         // 16 x 128 replicated bias rows
            #pragma unroll
            for (int i = 0; i < 8; i++) {
                int f = tid + i * 256;
                bt[f] = bias[n0 + (f & 127)];
            }
            __syncthreads();
            #pragma unroll
            for (int j = 0; j < 2; j++)
                wmma::load_matrix_sync(bias_frag[j], bt + wx * 32 + j * 16, 128,
                                       wmma::mem_row_major);
        }
        #pragma unroll
        for (int i = 0; i < 4; i++)
            #pragma unroll
            for (int j = 0; j < 2; j++) {
                #pragma unroll
                for (int e = 0; e < c_frag[i][j].num_elements; e++) {
                    float x = c_frag[i][j].x[e] * alpha;
                    if (EPI >= 1) x += bias_frag[j].x[e];
                    c_frag[i][j].x[e] = x;
                }
                wmma::store_matrix_sync(
                    Cf + (long long)(m0 + wy * 64 + i * 16) * N + n0 + wx * 32 + j * 16,
                    c_frag[i][j], N, wmma::mem_row_major);
            }
    } else {
        // ---- staging epilogue: bf16 out (position-dependent pack / GELU) ----
        constexpr int STG = 136;
        float* Stage = (float*)smem_raw;
        #pragma unroll
        for (int p = 0; p < 2; p++) {
            if (wy == p) {
                #pragma unroll
                for (int i = 0; i < 4; i++)
                    #pragma unroll
                    for (int j = 0; j < 2; j++)
                        wmma::store_matrix_sync(&Stage[(i * 16) * STG + wx * 32 + j * 16],
                                                c_frag[i][j], STG, wmma::mem_row_major);
            }
            __syncthreads();
            #pragma unroll
            for (int i = 0; i < 8; i++) {
                int f = tid + i * 256;            // 2048 float4 over 64x128
                int r = f >> 5, c4 = f & 31;
                float4 v = *(const float4*)&Stage[r * STG + c4 * 4];
                float o[4] = {v.x, v.y, v.z, v.w};
                #pragma unroll
                for (int e = 0; e < 4; e++) {
                    float x = o[e] * alpha;
                    if (EPI >= 1) x += bias[n0 + c4 * 4 + e];
                    if (EPI == 2) x = 0.5f * x * (1.0f + erff(x * 0.70710678118654752f));
                    o[e] = x;
                }
                const long long off = (long long)bz * sC + (long long)(m0 + p * 64 + r) * N + n0 + c4 * 4;
                ushort4 u;
                u.x = __bfloat16_as_ushort(__float2bfloat16_rn(o[0]));
                u.y = __bfloat16_as_ushort(__float2bfloat16_rn(o[1]));
                u.z = __bfloat16_as_ushort(__float2bfloat16_rn(o[2]));
                u.w = __bfloat16_as_ushort(__float2bfloat16_rn(o[3]));
                *(ushort4*)((bf16*)Cv + off) = u;
            }
            __syncthreads();
        }
    }
}

static const int GEMM_SMEM = 1024 + 3 * 36864;    // 111616 B -> 2 CTAs/SM

// ---------------------------------------------------------------------------
// fp32 -> bf16
// ---------------------------------------------------------------------------
__global__ __launch_bounds__(256)
void f2bf_kernel(const float* __restrict__ in, bf16* __restrict__ out, int n)
{
    int i = (blockIdx.x * 256 + threadIdx.x) * 4;
    if (i >= n) return;
    float4 v = *(const float4*)(in + i);
    ushort4 o;
    o.x = __bfloat16_as_ushort(__float2bfloat16_rn(v.x));
    o.y = __bfloat16_as_ushort(__float2bfloat16_rn(v.y));
    o.z = __bfloat16_as_ushort(__float2bfloat16_rn(v.z));
    o.w = __bfloat16_as_ushort(__float2bfloat16_rn(v.w));
    *(ushort4*)(out + i) = o;
}

// ---------------------------------------------------------------------------
// fp32 [R,C] -> bf16 [C,R]
// ---------------------------------------------------------------------------
__global__ __launch_bounds__(256)
void trans_f2bf_kernel(const float* __restrict__ in, bf16* __restrict__ out, int R, int C)
{
    __shared__ float t[32][33];
    const int bx = blockIdx.x, by = blockIdx.y;
    const int x = threadIdx.x & 31, y = threadIdx.x >> 5;
    #pragma unroll
    for (int i = 0; i < 4; i++) {
        int r = by * 32 + y + i * 8;
        t[y + i * 8][x] = in[(long long)r * C + bx * 32 + x];
    }
    __syncthreads();
    #pragma unroll
    for (int i = 0; i < 4; i++) {
        int cc = bx * 32 + y + i * 8;
        int rr = by * 32 + x;
        out[(long long)cc * R + rr] = __float2bfloat16_rn(t[x][y + i * 8]);
    }
}

// ---------------------------------------------------------------------------
// concat 3 fp32 vectors of DMODEL into one [3072]
// ---------------------------------------------------------------------------
__global__ __launch_bounds__(256)
void concat3_kernel(const float* __restrict__ a, const float* __restrict__ b,
                    const float* __restrict__ c, float* __restrict__ out)
{
    int i = blockIdx.x * 256 + threadIdx.x;
    if (i < DMODEL)            out[i] = a[i];
    else if (i < 2 * DMODEL)   out[i] = b[i - DMODEL];
    else if (i < 3 * DMODEL)   out[i] = c[i - 2 * DMODEL];
}

// ---------------------------------------------------------------------------
// bf16 batched strided transpose: V strip of QKV [B][T][ld] -> [B][D][T]
// ---------------------------------------------------------------------------
__global__ __launch_bounds__(256)
void transb_kernel(const bf16* __restrict__ in, bf16* __restrict__ out, int ld)
{
    __shared__ bf16 t[32][33];
    const int bx = blockIdx.x, by = blockIdx.y, bz = blockIdx.z;
    const bf16* pi = in + (long long)bz * TSEQ * ld;
    bf16* po = out + (long long)bz * DMODEL * TSEQ;
    const int x = threadIdx.x & 31, y = threadIdx.x >> 5;
    #pragma unroll
    for (int i = 0; i < 4; i++)
        t[y + i * 8][x] = pi[(long long)(by * 32 + y + i * 8) * ld + bx * 32 + x];
    __syncthreads();
    #pragma unroll
    for (int i = 0; i < 4; i++)
        po[(long long)(bx * 32 + y + i * 8) * TSEQ + by * 32 + x] = t[x][y + i * 8];
}

// ---------------------------------------------------------------------------
// Causal softmax: fp32 logits -> bf16 probs; zero tail to next 128 boundary
// ---------------------------------------------------------------------------
__global__ __launch_bounds__(256)
void softmax_causal_kernel(const float* __restrict__ S, bf16* __restrict__ P)
{
    __shared__ float buf[TSEQ];
    __shared__ float red[256];
    const int t = blockIdx.x, b = blockIdx.y;
    const float* row = S + ((long long)b * TSEQ + t) * TSEQ;
    bf16* prow = P + ((long long)b * TSEQ + t) * TSEQ;
    const int len = t + 1;
    const int zEnd = ((t >> 7) + 1) << 7;
    const int tid = threadIdx.x;

    float m = -1e30f;
    for (int s = tid; s < len; s += 256) { float v = row[s]; buf[s] = v; m = fmaxf(m, v); }
    red[tid] = m; __syncthreads();
    for (int o = 128; o > 0; o >>= 1) {
        if (tid < o) red[tid] = fmaxf(red[tid], red[tid + o]);
        __syncthreads();
    }
    m = red[0];
    __syncthreads();

    float sum = 0.0f;
    for (int s = tid; s < len; s += 256) { float e = expf(buf[s] - m); buf[s] = e; sum += e; }
    red[tid] = sum; __syncthreads();
    for (int o = 128; o > 0; o >>= 1) {
        if (tid < o) red[tid] += red[tid + o];
        __syncthreads();
    }
    const float inv = 1.0f / red[0];

    for (int s = tid; s < len; s += 256)        prow[s] = __float2bfloat16_rn(buf[s] * inv);
    for (int s = len + tid; s < zEnd; s += 256) prow[s] = __float2bfloat16_rn(0.0f);
}

// ---------------------------------------------------------------------------
// out = LayerNorm(Xa + Xb) * g + be ; optional bf16 copy
// ---------------------------------------------------------------------------
__global__ __launch_bounds__(256)
void add_ln_kernel(const float* __restrict__ Xa, const float* __restrict__ Xb,
                   const float* __restrict__ g,  const float* __restrict__ be,
                   float* __restrict__ out, bf16* __restrict__ out_bf)
{
    const int row = blockIdx.x;
    const int tid = threadIdx.x;
    const float* pa = Xa + (long long)row * DMODEL;
    const float* pb = Xb + (long long)row * DMODEL;

    float x[4];
    float s1 = 0.0f, s2 = 0.0f;
    #pragma unroll
    for (int i = 0; i < 4; i++) {
        int c = tid + i * 256;
        x[i] = pa[c] + pb[c];
        s1 += x[i];
        s2 += x[i] * x[i];
    }
    __shared__ float r1[256], r2[256];
    r1[tid] = s1; r2[tid] = s2; __syncthreads();
    for (int o = 128; o > 0; o >>= 1) {
        if (tid < o) { r1[tid] += r1[tid + o]; r2[tid] += r2[tid + o]; }
        __syncthreads();
    }
    const float mu  = r1[0] * (1.0f / DMODEL);
    const float var = r2[0] * (1.0f / DMODEL) - mu * mu;
    const float inv = rsqrtf(var + 1e-5f);

    float* po = out + (long long)row * DMODEL;
    #pragma unroll
    for (int i = 0; i < 4; i++) {
        int c = tid + i * 256;
        float v = (x[i] - mu) * inv * g[c] + be[c];
        po[c] = v;
        if (out_bf) out_bf[(long long)row * DMODEL + c] = __float2bfloat16_rn(v);
    }
}

// ---------------------------------------------------------------------------
// Host launch — multi-stream graph with fork/join for off-critical-path work
// ---------------------------------------------------------------------------
extern "C" void kernel_launch(void* const* d_in, const int* in_sizes, int n_in,
                              void* d_out, int out_size)
{
    (void)in_sizes; (void)n_in; (void)out_size;
    const float* X   = (const float*)d_in[0];
    const float* WQ  = (const float*)d_in[1];
    const float* bQ  = (const float*)d_in[2];
    const float* WK  = (const float*)d_in[3];
    const float* bK  = (const float*)d_in[4];
    const float* WV  = (const float*)d_in[5];
    const float* bV  = (const float*)d_in[6];
    const float* WO  = (const float*)d_in[7];
    const float* bO  = (const float*)d_in[8];
    const float* W1  = (const float*)d_in[9];
    const float* b1  = (const float*)d_in[10];
    const float* W2  = (const float*)d_in[11];
    const float* b2  = (const float*)d_in[12];
    const float* g1  = (const float*)d_in[13];
    const float* be1 = (const float*)d_in[14];
    const float* g2  = (const float*)d_in[15];
    const float* be2 = (const float*)d_in[16];
    float* out = (float*)d_out;

    bf16 *Xb, *Wqkv, *WOt, *W1t, *W2t, *QKV, *VTb, *Pb, *AOb, *H1b, *FFb;
    float *bqkv, *S, *O, *H1, *H2;
    cudaGetSymbolAddress((void**)&Xb,   g_Xb);
    cudaGetSymbolAddress((void**)&Wqkv, g_Wqkv);
    cudaGetSymbolAddress((void**)&bqkv, g_bqkv);
    cudaGetSymbolAddress((void**)&WOt,  g_WOt);
    cudaGetSymbolAddress((void**)&W1t,  g_W1t);
    cudaGetSymbolAddress((void**)&W2t,  g_W2t);
    cudaGetSymbolAddress((void**)&QKV,  g_QKV);
    cudaGetSymbolAddress((void**)&VTb,  g_VTb);
    cudaGetSymbolAddress((void**)&Pb,   g_Pb);
    cudaGetSymbolAddress((void**)&AOb,  g_AOb);
    cudaGetSymbolAddress((void**)&H1b,  g_H1b);
    cudaGetSymbolAddress((void**)&FFb,  g_FFb);
    cudaGetSymbolAddress((void**)&S,    g_S);
    cudaGetSymbolAddress((void**)&O,    g_O);
    cudaGetSymbolAddress((void**)&H1,   g_H1);
    cudaGetSymbolAddress((void**)&H2,   g_H2);

    cudaFuncSetAttribute(bfgemm_kernel<1, true,  false, false>, cudaFuncAttributeMaxDynamicSharedMemorySize, GEMM_SMEM);
    cudaFuncSetAttribute(bfgemm_kernel<0, false, true,  false>, cudaFuncAttributeMaxDynamicSharedMemorySize, GEMM_SMEM);
    cudaFuncSetAttribute(bfgemm_kernel<0, true,  false, true >, cudaFuncAttributeMaxDynamicSharedMemorySize, GEMM_SMEM);
    cudaFuncSetAttribute(bfgemm_kernel<1, false, false, false>, cudaFuncAttributeMaxDynamicSharedMemorySize, GEMM_SMEM);
    cudaFuncSetAttribute(bfgemm_kernel<2, true,  false, false>, cudaFuncAttributeMaxDynamicSharedMemorySize, GEMM_SMEM);

    // lazily-created side streams + events (host objects; no device memory)
    static cudaStream_t s2 = nullptr, s3 = nullptr;
    static cudaEvent_t evFork = nullptr, evW = nullptr, evQKV = nullptr, evT = nullptr;
    if (!s2) {
        cudaStreamCreateWithFlags(&s2, cudaStreamNonBlocking);
        cudaStreamCreateWithFlags(&s3, cudaStreamNonBlocking);
        cudaEventCreateWithFlags(&evFork, cudaEventDisableTiming);
        cudaEventCreateWithFlags(&evW,    cudaEventDisableTiming);
        cudaEventCreateWithFlags(&evQKV,  cudaEventDisableTiming);
        cudaEventCreateWithFlags(&evT,    cudaEventDisableTiming);
    }

    const dim3 blk256(256);

    // ---- fork stream-2: WO/W1/W2 transposes (needed only from O-proj on) ----
    cudaEventRecord(evFork, 0);
    cudaStreamWaitEvent(s2, evFork, 0);
    trans_f2bf_kernel<<<dim3(32, 32),  blk256, 0, s2>>>(WO, WOt, DMODEL, DMODEL);
    trans_f2bf_kernel<<<dim3(128, 32), blk256, 0, s2>>>(W1, W1t, DMODEL, DFF);
    trans_f2bf_kernel<<<dim3(32, 128), blk256, 0, s2>>>(W2, W2t, DFF, DMODEL);
    cudaEventRecord(evW, s2);

    // ---- main stream: only what QKV needs ----
    f2bf_kernel<<<NTOK * DMODEL / 1024, blk256>>>(X, Xb, NTOK * DMODEL);
    trans_f2bf_kernel<<<dim3(32, 32), blk256>>>(WQ, Wqkv,                       DMODEL, DMODEL);
    trans_f2bf_kernel<<<dim3(32, 32), blk256>>>(WK, Wqkv + DMODEL * DMODEL,     DMODEL, DMODEL);
    trans_f2bf_kernel<<<dim3(32, 32), blk256>>>(WV, Wqkv + 2 * DMODEL * DMODEL, DMODEL, DMODEL);
    concat3_kernel<<<12, blk256>>>(bQ, bK, bV, bqkv);

    const dim3 gQKV(DQKV / 128, NTOK / 128);               // 24 x 64
    const dim3 gProj(DMODEL / 128, NTOK / 128);            // 8 x 64
    const dim3 gS(TSEQ / 128, TSEQ / 128, NB);             // 16 x 16 x 4
    const dim3 gAV(DMODEL / 128, TSEQ / 128, NB);          // 8 x 16 x 4
    const dim3 gFF1(DFF / 128, NTOK / 128);                // 32 x 64

    const long long sQKV = (long long)TSEQ * DQKV;
    const long long sQK  = (long long)TSEQ * DMODEL;
    const long long sSS  = (long long)TSEQ * TSEQ;

    // fused QKV projection -> bf16 [8192, 3072]
    bfgemm_kernel<1, true, false, false><<<gQKV, blk256, GEMM_SMEM>>>(
        Xb, DMODEL, Wqkv, DMODEL, bqkv, QKV, NTOK, DQKV, DMODEL, 1.0f, 0, 0, 0);

    // ---- fork stream-3: V^T transpose concurrent with scores GEMM ----
    cudaEventRecord(evQKV, 0);
    cudaStreamWaitEvent(s3, evQKV, 0);
    transb_kernel<<<dim3(DMODEL / 32, TSEQ / 32, NB), blk256, 0, s3>>>(QKV + 2 * DMODEL, VTb, DQKV);
    cudaEventRecord(evT, s3);

    // scores = (Q @ K^T)/sqrt(D) -> fp32
    bfgemm_kernel<0, false, true, false><<<gS, blk256, GEMM_SMEM>>>(
        QKV, DQKV, QKV + DMODEL, DQKV, nullptr, S, TSEQ, TSEQ, DMODEL,
        0.03125f, sQKV, sQKV, sSS);

    // causal softmax -> bf16 probs
    softmax_causal_kernel<<<dim3(TSEQ, NB), blk256>>>(S, Pb);

    // join V^T before A@V
    cudaStreamWaitEvent(0, evT, 0);
    bfgemm_kernel<0, true, false, true><<<gAV, blk256, GEMM_SMEM>>>(
        Pb, TSEQ, VTb, TSEQ, nullptr, AOb, TSEQ, DMODEL, TSEQ,
        1.0f, sSS, (long long)DMODEL * TSEQ, sQK);

    // join weight transposes before O projection
    cudaStreamWaitEvent(0, evW, 0);
    bfgemm_kernel<1, false, false, false><<<gProj, blk256, GEMM_SMEM>>>(
        AOb, DMODEL, WOt, DMODEL, bO, O, NTOK, DMODEL, DMODEL, 1.0f, 0, 0, 0);

    // H1 = LN(O + X)
    add_ln_kernel<<<NTOK, blk256>>>(O, X, g1, be1, H1, H1b);

    // FF = gelu(H1 @ W1 + b1) -> bf16
    bfgemm_kernel<2, true, false, false><<<gFF1, blk256, GEMM_SMEM>>>(
        H1b, DMODEL, W1t, DMODEL, b1, FFb, NTOK, DFF, DMODEL, 1.0f, 0, 0, 0);

    // H2 = FF @ W2 + b2 -> fp32
    bfgemm_kernel<1, false, false, false><<<gProj, blk256, GEMM_SMEM>>>(
        FFb, DFF, W2t, DFF, b2, H2, NTOK, DMODEL, DFF, 1.0f, 0, 0, 0);

    // out = LN(H2 + H1)
    add_ln_kernel<<<NTOK, blk256>>>(H2, H1, g2, be2, out, nullptr);
}